// round 12
// baseline (speedup 1.0000x reference)
#include <cuda_runtime.h>
#include <cuda_bf16.h>
#include <math.h>
#include <stdint.h>

#define B_   2
#define N_   1536
#define DIM_ 1536
#define H_   8
#define D_   64
#define P_   3071      // 2N-1
#define RP_  3072      // padded row stride for rel tables
#define QT_  24        // N/64 tiles

// ---------------- device scratch (zero-initialized statics) ----------------
__device__ unsigned char g_tact[B_*QT_*QT_];
__device__ unsigned long long g_mbits[B_*QT_*QT_*64];

__device__ __nv_bfloat16 g_xh[B_*N_*DIM_];
__device__ __nv_bfloat16 g_xl[B_*N_*DIM_];
__device__ __nv_bfloat16 g_ph[RP_*192];           // pos_embed hi (row 3071 zero)
__device__ __nv_bfloat16 g_pl[RP_*192];
__device__ __nv_bfloat16 g_wh[1536*DIM_];
__device__ __nv_bfloat16 g_wl[1536*DIM_];
__device__ __nv_bfloat16 g_wrh[512*192];          // Wrel^T hi [512][192]
__device__ __nv_bfloat16 g_wrl[512*192];
__device__ __nv_bfloat16 g_woh[1536*512];
__device__ __nv_bfloat16 g_wol[1536*512];
__device__ __nv_bfloat16 g_ah[B_*N_*H_*D_];
__device__ __nv_bfloat16 g_al[B_*N_*H_*D_];
__device__ __nv_bfloat16 g_qh[B_*H_*N_*D_];       // q*scale + cb
__device__ __nv_bfloat16 g_ql[B_*H_*N_*D_];
__device__ __nv_bfloat16 g_qph[B_*H_*N_*D_];      // q*scale + pb
__device__ __nv_bfloat16 g_qpl[B_*H_*N_*D_];
__device__ __nv_bfloat16 g_kh[B_*H_*N_*D_];
__device__ __nv_bfloat16 g_kl[B_*H_*N_*D_];
__device__ __nv_bfloat16 g_vth[B_*H_*D_*N_];
__device__ __nv_bfloat16 g_vtl[B_*H_*D_*N_];
__device__ __nv_bfloat16 g_rh[H_*RP_*D_];         // rel_k hi [h][p(3072)][d]
__device__ __nv_bfloat16 g_rl[H_*RP_*D_];

// ---------------- helpers ----------------
__device__ __forceinline__ uint32_t smem_to_u32(const void* p) {
    uint32_t a;
    asm("{ .reg .u64 t; cvta.to.shared.u64 t, %1; cvt.u32.u64 %0, t; }" : "=r"(a) : "l"(p));
    return a;
}
__device__ __forceinline__ void cp_async16(uint32_t saddr, const void* g) {
    asm volatile("cp.async.cg.shared.global [%0], [%1], 16;" :: "r"(saddr), "l"(g));
}
#define CP_COMMIT() asm volatile("cp.async.commit_group;" ::: "memory")
#define CP_WAIT0()  asm volatile("cp.async.wait_group 0;" ::: "memory")
#define CP_WAIT1()  asm volatile("cp.async.wait_group 1;" ::: "memory")

__device__ __forceinline__ void mma_bf16(float* c, const uint32_t* a, const uint32_t* b) {
    asm volatile("mma.sync.aligned.m16n8k16.row.col.f32.bf16.bf16.f32 "
        "{%0,%1,%2,%3}, {%4,%5,%6,%7}, {%8,%9}, {%0,%1,%2,%3};"
        : "+f"(c[0]), "+f"(c[1]), "+f"(c[2]), "+f"(c[3])
        : "r"(a[0]), "r"(a[1]), "r"(a[2]), "r"(a[3]), "r"(b[0]), "r"(b[1]));
}
__device__ __forceinline__ void ldsm_x4(uint32_t* r, uint32_t addr) {
    asm volatile("ldmatrix.sync.aligned.m8n8.x4.shared.b16 {%0,%1,%2,%3}, [%4];"
        : "=r"(r[0]), "=r"(r[1]), "=r"(r[2]), "=r"(r[3]) : "r"(addr));
}
__device__ __forceinline__ void split2(float f0, float f1, uint32_t& hi, uint32_t& lo) {
    __nv_bfloat16 h0 = __float2bfloat16(f0), h1 = __float2bfloat16(f1);
    __nv_bfloat162 hh(h0, h1);
    hi = *(uint32_t*)&hh;
    __nv_bfloat16 l0 = __float2bfloat16(f0 - __bfloat162float(h0));
    __nv_bfloat16 l1 = __float2bfloat16(f1 - __bfloat162float(h1));
    __nv_bfloat162 ll(l0, l1);
    lo = *(uint32_t*)&ll;
}
__device__ __forceinline__ bool rd_mask(const unsigned char* p, long idx, int mt) {
    if (mt == 0) return p[idx] != 0;
    if (mt == 1) return ((const int*)p)[idx] != 0;
    return ((const float*)p)[idx] != 0.0f;
}
// swizzled smem address for 64B-row tiles (16B chunk granularity)
__device__ __forceinline__ uint32_t swz(uint32_t base, int r, int c) {
    return base + (uint32_t)r*64u + (uint32_t)((c ^ ((r >> 1) & 3)) << 4);
}

// ---------------- fused pre-processing kernel ----------------
#define NXB 4608
#define NPB 576
#define NTB 3840
#define NAB 288

__global__ void pre_kernel(const float* __restrict__ x, const float* __restrict__ pos,
                           const float* __restrict__ Wq, const float* __restrict__ Wk,
                           const float* __restrict__ Wv, const float* __restrict__ Wo,
                           const float* __restrict__ Wrel,
                           const unsigned char* __restrict__ lm,
                           const unsigned char* __restrict__ isg)
{
    __shared__ float t[32][33];
    __shared__ unsigned int cg[8];
    __shared__ unsigned char anyA[8];
    const int id = blockIdx.x;
    const int tid = threadIdx.x;

    if (id < NXB + NPB) {
        const float* s; __nv_bfloat16 *h, *l; int n4, base;
        __nv_bfloat16 *xh_p = g_xh, *xl_p = g_xl, *ph_p = g_ph, *pl_p = g_pl;
        if (id < NXB) { s = x; h = xh_p; l = xl_p; n4 = B_*N_*DIM_/4; base = id; }
        else          { s = pos; h = ph_p; l = pl_p; n4 = P_*192/4; base = id - NXB; }
        int i = base*256 + tid;
        if (i >= n4) return;
        float4 v = ((const float4*)s)[i];
        float a[4] = {v.x, v.y, v.z, v.w};
        __nv_bfloat16 hh[4], ll[4];
        #pragma unroll
        for (int j = 0; j < 4; j++) {
            hh[j] = __float2bfloat16(a[j]);
            ll[j] = __float2bfloat16(a[j] - __bfloat162float(hh[j]));
        }
        ((__nv_bfloat162*)h)[i*2+0] = __nv_bfloat162(hh[0], hh[1]);
        ((__nv_bfloat162*)h)[i*2+1] = __nv_bfloat162(hh[2], hh[3]);
        ((__nv_bfloat162*)l)[i*2+0] = __nv_bfloat162(ll[0], ll[1]);
        ((__nv_bfloat162*)l)[i*2+1] = __nv_bfloat162(ll[2], ll[3]);
    } else if (id < NXB + NPB + NTB) {
        int idx2 = id - NXB - NPB;
        int job = idx2 / 768, idx = idx2 % 768;
        const float* src; __nv_bfloat16 *dh, *dl;
        int R, C, c0, r0;
        if (job < 3) {
            src = (job == 0) ? Wq : (job == 1) ? Wk : Wv;
            dh = g_wh + (long)job*512*1536; dl = g_wl + (long)job*512*1536;
            R = 1536; C = 512;
            c0 = (idx & 15)*32; r0 = (idx >> 4)*32;
        } else if (job == 3) {
            src = Wo; dh = g_woh; dl = g_wol;
            R = 512; C = 1536;
            c0 = (idx % 48)*32; r0 = (idx / 48)*32;
        } else {
            if (idx >= 96) return;
            src = Wrel; dh = g_wrh; dl = g_wrl;
            R = 192; C = 512;
            c0 = (idx & 15)*32; r0 = (idx >> 4)*32;
        }
        int tx = tid & 31, ty = tid >> 5;
        #pragma unroll
        for (int i = 0; i < 4; i++)
            t[ty + i*8][tx] = src[(long)(r0 + ty + i*8)*C + c0 + tx];
        __syncthreads();
        #pragma unroll
        for (int i = 0; i < 4; i++) {
            int c = c0 + ty + i*8, r = r0 + tx;
            float v = t[tx][ty + i*8];
            __nv_bfloat16 hv = __float2bfloat16(v);
            dh[(long)c*R + r] = hv;
            dl[(long)c*R + r] = __float2bfloat16(v - __bfloat162float(hv));
        }
    } else {
        int tb = id - NXB - NPB - NTB;
        int g  = tid >> 6;
        int r  = tid & 63;
        int w  = tid >> 5;
        int lane = tid & 31;
        int tt = tb*4 + g;
        int jt = tt % QT_;
        int qt = (tt / QT_) % QT_;
        int b  = tt / (QT_*QT_);
        int i0 = qt*64, j0 = jt*64;
        unsigned int w0 = *(const unsigned int*)lm;
        int mt;
        if ((w0 & 0xFFu) == 1u && ((w0 >> 8) & 0xFFu) == 1u) mt = 0;
        else if (w0 == 1u) mt = 1;
        else mt = 2;

        bool cpred = rd_mask(isg, (long)b*N_ + j0 + r, mt);
        unsigned int cw = __ballot_sync(0xffffffffu, cpred);
        if (lane == 0) cg[w] = cw;

        bool rg = rd_mask(isg, (long)b*N_ + i0 + r, mt);

        unsigned long long rowbits = 0ull;
        if (mt == 0) {
            const uint4* rp = (const uint4*)(lm + (long)(i0 + r)*N_ + j0);
            #pragma unroll
            for (int q = 0; q < 4; q++) {
                uint4 v = rp[q];
                unsigned int ws[4] = {v.x, v.y, v.z, v.w};
                #pragma unroll
                for (int k = 0; k < 4; k++) {
                    unsigned int nz  = __vcmpne4(ws[k], 0u) & 0x01010101u;
                    unsigned int nib = (nz * 0x01020408u) >> 24;
                    rowbits |= (unsigned long long)(nib & 0xFu) << (q*16 + k*4);
                }
            }
        } else {
            for (int c = 0; c < 64; c++)
                rowbits |= (unsigned long long)(rd_mask(lm, (long)(i0+r)*N_ + j0 + c, mt) ? 1 : 0) << c;
        }
        __syncthreads();
        unsigned long long colbits = (unsigned long long)cg[g*2]
                                   | ((unsigned long long)cg[g*2+1] << 32);
        unsigned long long bits = rg ? ~0ull : (rowbits | colbits);
        g_mbits[(long)tt*64 + r] = bits;
        unsigned int anyw = __ballot_sync(0xffffffffu, bits != 0ull);
        if (lane == 0) anyA[w] = anyw ? 1 : 0;
        __syncthreads();
        if (r == 0) g_tact[tt] = (unsigned char)(anyA[g*2] | anyA[g*2+1]);
    }
}

// ---------------- warp-MMA bf16 split-precision GEMM (3-stage, swizzled) ----------------
#define TBYTES 8192              // 128 rows x 64 B
#define STAGE  (4*TBYTES)        // 32768
#define NSTG   3
#define WG_SMEM (NSTG*STAGE)     // 98304

__global__ __launch_bounds__(256, 2)
void wmma_gemm(const __nv_bfloat16* __restrict__ Ah, const __nv_bfloat16* __restrict__ Al,
               const __nv_bfloat16* __restrict__ Bh, const __nv_bfloat16* __restrict__ Bl,
               const float* __restrict__ bias, const float* __restrict__ bias2,
               float* __restrict__ Cout, int K, int mode)
{
    extern __shared__ char smem[];
    const uint32_t sb = smem_to_u32(smem);
    const int tid = threadIdx.x;
    const int lane = tid & 31;
    const int wid = tid >> 5;
    const int warp_m = wid >> 2;
    const int warp_n = wid & 3;
    const int grp = lane >> 2;
    const int tig = lane & 3;

    int m0, n0, Keff = K, mode_eff = mode;
    const char* srcs[4];
    if (mode == 0) {
        int id = blockIdx.x;
        if (id < 288) {
            m0 = (id % 24) * 128; n0 = (id / 24) * 128;
            srcs[0] = (const char*)Ah; srcs[1] = (const char*)Al;
            srcs[2] = (const char*)Bh; srcs[3] = (const char*)Bl;
        } else {
            id -= 288;
            m0 = (id % 24) * 128; n0 = (id / 24) * 128;
            srcs[0] = (const char*)g_ph;  srcs[1] = (const char*)g_pl;
            srcs[2] = (const char*)g_wrh; srcs[3] = (const char*)g_wrl;
            Keff = 192; mode_eff = 2;
        }
    } else {
        m0 = blockIdx.x * 128; n0 = blockIdx.y * 128;
        srcs[0] = (const char*)Ah; srcs[1] = (const char*)Al;
        srcs[2] = (const char*)Bh; srcs[3] = (const char*)Bl;
    }

    const int arow_l = lane & 15;
    const int achk_l = lane >> 4;
    const int brow_l = ((lane >> 4) << 3) + (lane & 7);
    const int bchk_l = (lane >> 3) & 1;

    const int rb[4] = {m0, m0, n0, n0};
    const long rowB = (long)Keff * 2;

    auto issue_stage = [&](int kt, int st) {
        const uint32_t sbase = sb + st*STAGE;
        #pragma unroll
        for (int l = 0; l < 8; l++) {
            int i = tid + l*256;
            int t = i >> 9, r = (i >> 2) & 127, c = i & 3;
            const char* g = srcs[t] + (long)(rb[t] + r)*rowB + kt*64 + c*16;
            cp_async16(swz(sbase + t*TBYTES, r, c), g);
        }
        CP_COMMIT();
    };

    float acc[4][4][4];
    #pragma unroll
    for (int i = 0; i < 4; i++)
        #pragma unroll
        for (int j = 0; j < 4; j++)
            #pragma unroll
            for (int e = 0; e < 4; e++) acc[i][j][e] = 0.f;

    const int nk = Keff / 32;
    issue_stage(0, 0);
    issue_stage(1, 1);

    for (int kt = 0; kt < nk; kt++) {
        CP_WAIT1();
        __syncthreads();
        if (kt + 2 < nk) issue_stage(kt + 2, (kt + 2) % NSTG);

        const uint32_t stg = sb + (kt % NSTG)*STAGE;
        const uint32_t aoffh = stg + 0*TBYTES;
        const uint32_t aoffl = stg + 1*TBYTES;
        const uint32_t boffh = stg + 2*TBYTES;
        const uint32_t boffl = stg + 3*TBYTES;

        #pragma unroll
        for (int ks = 0; ks < 2; ks++) {
            uint32_t bh[4][2], bl[4][2];
            #pragma unroll
            for (int jp = 0; jp < 2; jp++) {
                int brw = warp_n*32 + jp*16 + brow_l;
                int bck = ks*2 + bchk_l;
                uint32_t r4[4];
                ldsm_x4(r4, swz(boffh, brw, bck));
                bh[2*jp][0] = r4[0]; bh[2*jp][1] = r4[1];
                bh[2*jp+1][0] = r4[2]; bh[2*jp+1][1] = r4[3];
                ldsm_x4(r4, swz(boffl, brw, bck));
                bl[2*jp][0] = r4[0]; bl[2*jp][1] = r4[1];
                bl[2*jp+1][0] = r4[2]; bl[2*jp+1][1] = r4[3];
            }
            #pragma unroll
            for (int i = 0; i < 4; i++) {
                int arw = warp_m*64 + i*16 + arow_l;
                int ack = ks*2 + achk_l;
                uint32_t ah[4], al[4];
                ldsm_x4(ah, swz(aoffh, arw, ack));
                ldsm_x4(al, swz(aoffl, arw, ack));
                // stream-major ordering: same-acc reuse distance 4 (was 1)
                #pragma unroll
                for (int j = 0; j < 4; j++) mma_bf16(acc[i][j], ah, bh[j]);
                #pragma unroll
                for (int j = 0; j < 4; j++) mma_bf16(acc[i][j], ah, bl[j]);
                #pragma unroll
                for (int j = 0; j < 4; j++) mma_bf16(acc[i][j], al, bh[j]);
            }
        }
    }

    // epilogue
    #pragma unroll
    for (int i = 0; i < 4; i++) {
        #pragma unroll
        for (int j = 0; j < 4; j++) {
            const int r0 = m0 + warp_m*64 + i*16 + grp;
            const int c0 = n0 + warp_n*32 + j*8 + 2*tig;
            #pragma unroll
            for (int half = 0; half < 2; half++) {
                const int row = r0 + half*8;
                float v0 = acc[i][j][half*2 + 0];
                float v1 = acc[i][j][half*2 + 1];
                if (mode_eff == 1) {
                    Cout[(long)row*1536 + c0]     = v0 + bias[c0];
                    Cout[(long)row*1536 + c0 + 1] = v1 + bias[c0 + 1];
                } else if (mode_eff == 2) {
                    const int h = c0 >> 6, d = c0 & 63;
                    uint32_t hi, lo; split2(v0, v1, hi, lo);
                    long idx = ((long)h*RP_ + row)*D_ + d;
                    *(uint32_t*)&g_rh[idx] = hi;
                    *(uint32_t*)&g_rl[idx] = lo;
                } else {
                    const int sel = c0 >> 9, pc = c0 & 511;
                    const int h = pc >> 6, d = pc & 63;
                    const int bb = (row >= N_) ? 1 : 0;
                    const int ii = row - bb*N_;
                    const int bhd = bb*H_ + h;
                    if (sel == 0) {
                        float s0 = v0*0.125f, s1 = v1*0.125f;
                        long idx = ((long)bhd*N_ + ii)*D_ + d;
                        uint32_t hi, lo;
                        split2(s0 + bias[pc], s1 + bias[pc + 1], hi, lo);
                        *(uint32_t*)&g_qh[idx] = hi;
                        *(uint32_t*)&g_ql[idx] = lo;
                        split2(s0 + bias2[pc], s1 + bias2[pc + 1], hi, lo);
                        *(uint32_t*)&g_qph[idx] = hi;
                        *(uint32_t*)&g_qpl[idx] = lo;
                    } else if (sel == 1) {
                        uint32_t hi, lo; split2(v0, v1, hi, lo);
                        long idx = ((long)bhd*N_ + ii)*D_ + d;
                        *(uint32_t*)&g_kh[idx] = hi;
                        *(uint32_t*)&g_kl[idx] = lo;
                    } else {
                        __nv_bfloat16 h0 = __float2bfloat16(v0);
                        __nv_bfloat16 h1 = __float2bfloat16(v1);
                        long i0x = ((long)bhd*D_ + d)*N_ + ii;
                        long i1x = ((long)bhd*D_ + d + 1)*N_ + ii;
                        g_vth[i0x] = h0;
                        g_vth[i1x] = h1;
                        g_vtl[i0x] = __float2bfloat16(v0 - __bfloat162float(h0));
                        g_vtl[i1x] = __float2bfloat16(v1 - __bfloat162float(h1));
                    }
                }
            }
        }
    }
}

// ---------------- mma.sync flash attention (ldmatrix) ----------------
#define AK_H   0u
#define AK_L   9216u
#define AVT_H  18432u
#define AVT_L  27648u
#define AR_H   36864u
#define AR_L   55296u
#define AG     73728u
#define ATTN2_SMEM (73728 + 64*132*4)

__global__ __launch_bounds__(128, 2)
void attn_mma()
{
    extern __shared__ char sm2[];
    const uint32_t sb = smem_to_u32(sm2);
    float* sG = (float*)(sm2 + AG);

    const int tid = threadIdx.x;
    const int lane = tid & 31;
    const int w = tid >> 5;
    const int grp = lane >> 2;
    const int tig = lane & 3;
    const int qt = blockIdx.x;
    const int bh = blockIdx.y;
    const int b = bh >> 3, h = bh & 7;
    const int i0 = qt * 64;

    const int brow_l = ((lane >> 4) << 3) + (lane & 7);
    const int bcol_l = ((lane >> 3) & 1) * 16;

    // ---- Q fragments (persistent): content (cb) + positional (pb) ----
    const __nv_bfloat16* qbh = g_qh  + (long)bh*N_*D_;
    const __nv_bfloat16* qbl = g_ql  + (long)bh*N_*D_;
    const __nv_bfloat16* pqh = g_qph + (long)bh*N_*D_;
    const __nv_bfloat16* pql = g_qpl + (long)bh*N_*D_;
    const int rq0 = i0 + w*16 + grp, rq1 = rq0 + 8;
    uint32_t qfh[4][4], qfl[4][4], qgh[4][4], qgl[4][4];
    #pragma unroll
    for (int kf = 0; kf < 4; kf++) {
        qfh[kf][0] = *(const uint32_t*)(qbh + (long)rq0*D_ + kf*16 + 2*tig);
        qfh[kf][1] = *(const uint32_t*)(qbh + (long)rq1*D_ + kf*16 + 2*tig);
        qfh[kf][2] = *(const uint32_t*)(qbh + (long)rq0*D_ + kf*16 + 8 + 2*tig);
        qfh[kf][3] = *(const uint32_t*)(qbh + (long)rq1*D_ + kf*16 + 8 + 2*tig);
        qfl[kf][0] = *(const uint32_t*)(qbl + (long)rq0*D_ + kf*16 + 2*tig);
        qfl[kf][1] = *(const uint32_t*)(qbl + (long)rq1*D_ + kf*16 + 2*tig);
        qfl[kf][2] = *(const uint32_t*)(qbl + (long)rq0*D_ + kf*16 + 8 + 2*tig);
        qfl[kf][3] = *(const uint32_t*)(qbl + (long)rq1*D_ + kf*16 + 8 + 2*tig);
        qgh[kf][0] = *(const uint32_t*)(pqh + (long)rq0*D_ + kf*16 + 2*tig);
        qgh[kf][1] = *(const uint32_t*)(pqh + (long)rq1*D_ + kf*16 + 2*tig);
        qgh[kf][2] = *(const uint32_t*)(pqh + (long)rq0*D_ + kf*16 + 8 + 2*tig);
        qgh[kf][3] = *(const uint32_t*)(pqh + (long)rq1*D_ + kf*16 + 8 + 2*tig);
        qgl[kf][0] = *(const uint32_t*)(pql + (long)rq0*D_ + kf*16 + 2*tig);
        qgl[kf][1] = *(const uint32_t*)(pql + (long)rq1*D_ + kf*16 + 2*tig);
        qgl[kf][2] = *(const uint32_t*)(pql + (long)rq0*D_ + kf*16 + 8 + 2*tig);
        qgl[kf][3] = *(const uint32_t*)(pql + (long)rq1*D_ + kf*16 + 8 + 2*tig);
    }

    float o[8][4];
    #pragma unroll
    for (int nf = 0; nf < 8; nf++)
        #pragma unroll
        for (int e = 0; e < 4; e++) o[nf][e] = 0.f;
    float mrow[2] = {-1e30f, -1e30f};
    float lrow[2] = {0.f, 0.f};

    const unsigned char* tact = &g_tact[(b*QT_ + qt)*QT_];
    const long kbase  = (long)bh*N_*D_;
    const long vbase  = (long)bh*D_*N_;
    const long rbase  = (long)h*RP_*D_;

    for (int jt = 0; jt < QT_; jt++) {
        if (!tact[jt]) continue;
        const int j0 = jt*64;
        const int p0 = j0 - i0 + (N_ - 1) - 63;

        __syncthreads();
        #pragma unroll
        for (int l = 0; l < 4; l++) {
            int i = tid + l*128;
            int r = i >> 3, c = i & 7;
            long krow = (kbase + (long)(j0 + r)*D_)*2;
            long vrow = (vbase + (long)r*N_ + j0)*2;
            cp_async16(sb + AK_H  + r*144 + c*16, (const char*)g_kh  + krow + c*16);
            cp_async16(sb + AK_L  + r*144 + c*16, (const char*)g_kl  + krow + c*16);
            cp_async16(sb + AVT_H + r*144 + c*16, (const char*)g_vth + vrow + c*16);
            cp_async16(sb + AVT_L + r*144 + c*16, (const char*)g_vtl + vrow + c*16);
        }
        #pragma unroll
        for (int l = 0; l < 8; l++) {
            int i = tid + l*128;
            int r = i >> 3, c = i & 7;
            long rrow = (rbase + (long)(p0 + r)*D_)*2;
            cp_async16(sb + AR_H + r*144 + c*16, (const char*)g_rh + rrow + c*16);
            cp_async16(sb + AR_L + r*144 + c*16, (const char*)g_rl + rrow + c*16);
        }
        CP_COMMIT();

        const unsigned long long* mb = g_mbits + ((long)(b*QT_ + qt)*QT_ + jt)*64;
        unsigned long long mw0 = mb[w*16 + grp];
        unsigned long long mw1 = mb[w*16 + grp + 8];

        CP_WAIT0();
        __syncthreads();

        // ---- content logits: Qc @ K^T (acc-interleaved stream order) ----
        float ca[8][4];
        #pragma unroll
        for (int nf = 0; nf < 8; nf++)
            #pragma unroll
            for (int e = 0; e < 4; e++) ca[nf][e] = 0.f;
        #pragma unroll
        for (int kf = 0; kf < 4; kf++) {
            #pragma unroll
            for (int np = 0; np < 4; np++) {
                uint32_t ro = (uint32_t)(np*16 + brow_l)*144 + kf*32 + bcol_l;
                uint32_t kh4[4], kl4[4];
                ldsm_x4(kh4, sb + AK_H + ro);
                ldsm_x4(kl4, sb + AK_L + ro);
                mma_bf16(ca[2*np],   qfh[kf], &kh4[0]);
                mma_bf16(ca[2*np+1], qfh[kf], &kh4[2]);
                mma_bf16(ca[2*np],   qfh[kf], &kl4[0]);
                mma_bf16(ca[2*np+1], qfh[kf], &kl4[2]);
                mma_bf16(ca[2*np],   qfl[kf], &kh4[0]);
                mma_bf16(ca[2*np+1], qfl[kf], &kh4[2]);
            }
        }

        // ---- G = Qp @ Rband^T ----
        const int grow = w*16 + grp;
        #pragma unroll
        for (int gh = 0; gh < 2; gh++) {
            float ga[8][4];
            #pragma unroll
            for (int nf = 0; nf < 8; nf++)
                #pragma unroll
                for (int e = 0; e < 4; e++) ga[nf][e] = 0.f;
            #pragma unroll
            for (int kf = 0; kf < 4; kf++) {
                #pragma unroll
                for (int np = 0; np < 4; np++) {
                    uint32_t ro = (uint32_t)(gh*64 + np*16 + brow_l)*144 + kf*32 + bcol_l;
                    uint32_t rh4[4], rl4[4];
                    ldsm_x4(rh4, sb + AR_H + ro);
                    ldsm_x4(rl4, sb + AR_L + ro);
                    mma_bf16(ga[2*np],   qgh[kf], &rh4[0]);
                    mma_bf16(ga[2*np+1], qgh[kf], &rh4[2]);
                    mma_bf16(ga[2*np],   qgh[kf], &rl4[0]);
                    mma_bf16(ga[2*np+1], qgh[kf], &rl4[2]);
                    mma_bf16(ga[2*np],   qgl[kf], &rh4[0]);
                    mma_bf16(ga[2*np+1], qgl[kf], &rh4[2]);
                }
            }
            #pragma unroll
            for (int nf = 0; nf < 8; nf++) {
                int col = gh*64 + 8*nf + 2*tig;
                sG[grow*132 + col]           = ga[nf][0];
                sG[grow*132 + col + 1]       = ga[nf][1];
                sG[(grow + 8)*132 + col]     = ga[nf][2];
                sG[(grow + 8)*132 + col + 1] = ga[nf][3];
            }
        }
        __syncwarp();

        // ---- gather + mask + online softmax ----
        float pv0[16], pv1[16];
        #pragma unroll
        for (int h2 = 0; h2 < 2; h2++) {
            const int rl = grow + 8*h2;
            const unsigned long long mw = h2 ? mw1 : mw0;
            float* pvv = h2 ? pv1 : pv0;
            float lg[16];
            float tmax = -1e30f;
            #pragma unroll
            for (int nf = 0; nf < 8; nf++) {
                #pragma unroll
                for (int e = 0; e < 2; e++) {
                    int c = 8*nf + 2*tig + e;
                    int pp = c - rl + 63;
                    float val = ca[nf][2*h2 + e] + sG[rl*132 + pp];
                    bool act = (mw >> c) & 1ull;
                    float lv = act ? val : -1e30f;
                    lg[nf*2 + e] = lv;
                    tmax = fmaxf(tmax, lv);
                }
            }
            tmax = fmaxf(tmax, __shfl_xor_sync(0xffffffffu, tmax, 1));
            tmax = fmaxf(tmax, __shfl_xor_sync(0xffffffffu, tmax, 2));
            float nm = fmaxf(mrow[h2], tmax);
            float corr = __expf(mrow[h2] - nm);
            mrow[h2] = nm;
            float ps = 0.f;
            #pragma unroll
            for (int e2 = 0; e2 < 16; e2++) {
                float p = (lg[e2] <= -1e29f) ? 0.f : __expf(lg[e2] - nm);
                pvv[e2] = p;
                ps += p;
            }
            ps += __shfl_xor_sync(0xffffffffu, ps, 1);
            ps += __shfl_xor_sync(0xffffffffu, ps, 2);
            lrow[h2] = lrow[h2]*corr + ps;
            #pragma unroll
            for (int nf = 0; nf < 8; nf++) {
                o[nf][2*h2]     *= corr;
                o[nf][2*h2 + 1] *= corr;
            }
        }

        // ---- P fragments ----
        uint32_t pfh[4][4], pfl[4][4];
        #pragma unroll
        for (int kf = 0; kf < 4; kf++) {
            split2(pv0[(2*kf)*2],   pv0[(2*kf)*2+1],   pfh[kf][0], pfl[kf][0]);
            split2(pv1[(2*kf)*2],   pv1[(2*kf)*2+1],   pfh[kf][1], pfl[kf][1]);
            split2(pv0[(2*kf+1)*2], pv0[(2*kf+1)*2+1], pfh[kf][2], pfl[kf][2]);
            split2(pv1[(2*kf+1)*2], pv1[(2*kf+1)*2+1], pfh[kf][3], pfl[kf][3]);
        }

        // ---- PV ----
        #pragma unroll
        for (int kf = 0; kf < 4; kf++) {
            #pragma unroll
            for (int np = 0; np < 4; np++) {
                uint32_t ro = (uint32_t)(np*16 + brow_l)*144 + kf*32 + bcol_l;
                uint32_t vh4[4], vl4[4];
                ldsm_x4(vh4, sb + AVT_H + ro);
                ldsm_x4(vl4, sb + AVT_L + ro);
                mma_bf16(o[2*np],   pfh[kf], &vh4[0]);
                mma_bf16(o[2*np+1], pfh[kf], &vh4[2]);
                mma_bf16(o[2*np],   pfh[kf], &vl4[0]);
                mma_bf16(o[2*np+1], pfh[kf], &vl4[2]);
                mma_bf16(o[2*np],   pfl[kf], &vh4[0]);
                mma_bf16(o[2*np+1], pfl[kf], &vh4[2]);
            }
        }
    }

    // ---- epilogue ----
    #pragma unroll
    for (int h2 = 0; h2 < 2; h2++) {
        float inv = 1.0f / lrow[h2];
        int rl = w*16 + grp + 8*h2;
        long rowbase = ((long)(b*N_ + i0 + rl))*(H_*D_) + h*D_;
        #pragma unroll
        for (int nf = 0; nf < 8; nf++) {
            float f0 = o[nf][2*h2]     * inv;
            float f1 = o[nf][2*h2 + 1] * inv;
            uint32_t hi, lo; split2(f0, f1, hi, lo);
            long idx = rowbase + 8*nf + 2*tig;
            *(uint32_t*)&g_ah[idx] = hi;
            *(uint32_t*)&g_al[idx] = lo;
        }
    }
}

// ---------------- launcher ----------------
extern "C" void kernel_launch(void* const* d_in, const int* in_sizes, int n_in,
                              void* d_out, int out_size)
{
    const float* x    = (const float*)d_in[0];
    const float* Wq   = (const float*)d_in[1];
    const float* Wk   = (const float*)d_in[2];
    const float* Wv   = (const float*)d_in[3];
    const float* Wrel = (const float*)d_in[4];
    const float* cb   = (const float*)d_in[5];
    const float* pb   = (const float*)d_in[6];
    const float* Wo   = (const float*)d_in[7];
    const float* bo   = (const float*)d_in[8];
    const float* pos  = (const float*)d_in[9];
    const unsigned char* lmu = (const unsigned char*)d_in[10];
    const unsigned char* isg = (const unsigned char*)d_in[11];
    float* out = (float*)d_out;

    cudaFuncSetAttribute(wmma_gemm, cudaFuncAttributeMaxDynamicSharedMemorySize, WG_SMEM);
    cudaFuncSetAttribute(attn_mma, cudaFuncAttributeMaxDynamicSharedMemorySize, ATTN2_SMEM);

    __nv_bfloat16 *xh_p, *xl_p, *wh_p, *wl_p, *woh_p, *wol_p, *ah_p, *al_p;
    cudaGetSymbolAddress((void**)&xh_p,  g_xh);
    cudaGetSymbolAddress((void**)&xl_p,  g_xl);
    cudaGetSymbolAddress((void**)&wh_p,  g_wh);
    cudaGetSymbolAddress((void**)&wl_p,  g_wl);
    cudaGetSymbolAddress((void**)&woh_p, g_woh);
    cudaGetSymbolAddress((void**)&wol_p, g_wol);
    cudaGetSymbolAddress((void**)&ah_p,  g_ah);
    cudaGetSymbolAddress((void**)&al_p,  g_al);

    pre_kernel<<<NXB + NPB + NTB + NAB, 256>>>(x, pos, Wq, Wk, Wv, Wo, Wrel,
                                               lmu, isg);                    // 1
    wmma_gemm<<<384, 256, WG_SMEM>>>(xh_p, xl_p, wh_p, wl_p,
                                     cb, pb, nullptr, DIM_, 0);              // 2
    attn_mma<<<dim3(QT_, B_*H_), 128, ATTN2_SMEM>>>();                       // 3
    wmma_gemm<<<dim3(24, 12), 256, WG_SMEM>>>(ah_p, al_p, woh_p, wol_p,
                                              bo, nullptr, out, 512, 1);     // 4
}

// round 13
// speedup vs baseline: 1.0578x; 1.0578x over previous
#include <cuda_runtime.h>
#include <cuda_bf16.h>
#include <math.h>
#include <stdint.h>

#define B_   2
#define N_   1536
#define DIM_ 1536
#define H_   8
#define D_   64
#define P_   3071      // 2N-1
#define RP_  3072      // padded row stride for rel tables
#define QT_  24        // N/64 tiles

// ---------------- device scratch (zero-initialized statics) ----------------
__device__ unsigned char g_tact[B_*QT_*QT_];
__device__ unsigned long long g_mbits[B_*QT_*QT_*64];

__device__ __nv_bfloat16 g_xh[B_*N_*DIM_];
__device__ __nv_bfloat16 g_xl[B_*N_*DIM_];
__device__ __nv_bfloat16 g_ph[RP_*192];           // pos_embed hi (row 3071 zero)
__device__ __nv_bfloat16 g_pl[RP_*192];
__device__ __nv_bfloat16 g_wh[1536*DIM_];
__device__ __nv_bfloat16 g_wl[1536*DIM_];
__device__ __nv_bfloat16 g_wrh[512*192];          // Wrel^T hi [512][192]
__device__ __nv_bfloat16 g_wrl[512*192];
__device__ __nv_bfloat16 g_woh[1536*512];
__device__ __nv_bfloat16 g_wol[1536*512];
__device__ __nv_bfloat16 g_ah[B_*N_*H_*D_];
__device__ __nv_bfloat16 g_al[B_*N_*H_*D_];
__device__ __nv_bfloat16 g_qh[B_*H_*N_*D_];       // q*scale + cb
__device__ __nv_bfloat16 g_ql[B_*H_*N_*D_];
__device__ __nv_bfloat16 g_qph[B_*H_*N_*D_];      // q*scale + pb
__device__ __nv_bfloat16 g_qpl[B_*H_*N_*D_];
__device__ __nv_bfloat16 g_kh[B_*H_*N_*D_];
__device__ __nv_bfloat16 g_kl[B_*H_*N_*D_];
__device__ __nv_bfloat16 g_vth[B_*H_*D_*N_];
__device__ __nv_bfloat16 g_vtl[B_*H_*D_*N_];
__device__ __nv_bfloat16 g_rh[H_*RP_*D_];         // rel_k hi [h][p(3072)][d]
__device__ __nv_bfloat16 g_rl[H_*RP_*D_];

// ---------------- helpers ----------------
__device__ __forceinline__ uint32_t smem_to_u32(const void* p) {
    uint32_t a;
    asm("{ .reg .u64 t; cvta.to.shared.u64 t, %1; cvt.u32.u64 %0, t; }" : "=r"(a) : "l"(p));
    return a;
}
__device__ __forceinline__ void cp_async16(uint32_t saddr, const void* g) {
    asm volatile("cp.async.cg.shared.global [%0], [%1], 16;" :: "r"(saddr), "l"(g));
}
#define CP_COMMIT() asm volatile("cp.async.commit_group;" ::: "memory")
#define CP_WAIT0()  asm volatile("cp.async.wait_group 0;" ::: "memory")
#define CP_WAIT1()  asm volatile("cp.async.wait_group 1;" ::: "memory")

__device__ __forceinline__ void mma_bf16(float* c, const uint32_t* a, const uint32_t* b) {
    asm volatile("mma.sync.aligned.m16n8k16.row.col.f32.bf16.bf16.f32 "
        "{%0,%1,%2,%3}, {%4,%5,%6,%7}, {%8,%9}, {%0,%1,%2,%3};"
        : "+f"(c[0]), "+f"(c[1]), "+f"(c[2]), "+f"(c[3])
        : "r"(a[0]), "r"(a[1]), "r"(a[2]), "r"(a[3]), "r"(b[0]), "r"(b[1]));
}
__device__ __forceinline__ void ldsm_x4(uint32_t* r, uint32_t addr) {
    asm volatile("ldmatrix.sync.aligned.m8n8.x4.shared.b16 {%0,%1,%2,%3}, [%4];"
        : "=r"(r[0]), "=r"(r[1]), "=r"(r[2]), "=r"(r[3]) : "r"(addr));
}
__device__ __forceinline__ void split2(float f0, float f1, uint32_t& hi, uint32_t& lo) {
    __nv_bfloat16 h0 = __float2bfloat16(f0), h1 = __float2bfloat16(f1);
    __nv_bfloat162 hh(h0, h1);
    hi = *(uint32_t*)&hh;
    __nv_bfloat16 l0 = __float2bfloat16(f0 - __bfloat162float(h0));
    __nv_bfloat16 l1 = __float2bfloat16(f1 - __bfloat162float(h1));
    __nv_bfloat162 ll(l0, l1);
    lo = *(uint32_t*)&ll;
}
__device__ __forceinline__ bool rd_mask(const unsigned char* p, long idx, int mt) {
    if (mt == 0) return p[idx] != 0;
    if (mt == 1) return ((const int*)p)[idx] != 0;
    return ((const float*)p)[idx] != 0.0f;
}
// swizzled smem address for 64B-row tiles (16B chunk granularity)
__device__ __forceinline__ uint32_t swz(uint32_t base, int r, int c) {
    return base + (uint32_t)r*64u + (uint32_t)((c ^ ((r >> 1) & 3)) << 4);
}

// ---------------- fused pre-processing kernel ----------------
#define NXB 4608
#define NPB 576
#define NTB 3840
#define NAB 288

__global__ void pre_kernel(const float* __restrict__ x, const float* __restrict__ pos,
                           const float* __restrict__ Wq, const float* __restrict__ Wk,
                           const float* __restrict__ Wv, const float* __restrict__ Wo,
                           const float* __restrict__ Wrel,
                           const unsigned char* __restrict__ lm,
                           const unsigned char* __restrict__ isg)
{
    __shared__ float t[32][33];
    __shared__ unsigned int cg[8];
    __shared__ unsigned char anyA[8];
    const int id = blockIdx.x;
    const int tid = threadIdx.x;

    if (id < NXB + NPB) {
        const float* s; __nv_bfloat16 *h, *l; int n4, base;
        __nv_bfloat16 *xh_p = g_xh, *xl_p = g_xl, *ph_p = g_ph, *pl_p = g_pl;
        if (id < NXB) { s = x; h = xh_p; l = xl_p; n4 = B_*N_*DIM_/4; base = id; }
        else          { s = pos; h = ph_p; l = pl_p; n4 = P_*192/4; base = id - NXB; }
        int i = base*256 + tid;
        if (i >= n4) return;
        float4 v = ((const float4*)s)[i];
        float a[4] = {v.x, v.y, v.z, v.w};
        __nv_bfloat16 hh[4], ll[4];
        #pragma unroll
        for (int j = 0; j < 4; j++) {
            hh[j] = __float2bfloat16(a[j]);
            ll[j] = __float2bfloat16(a[j] - __bfloat162float(hh[j]));
        }
        ((__nv_bfloat162*)h)[i*2+0] = __nv_bfloat162(hh[0], hh[1]);
        ((__nv_bfloat162*)h)[i*2+1] = __nv_bfloat162(hh[2], hh[3]);
        ((__nv_bfloat162*)l)[i*2+0] = __nv_bfloat162(ll[0], ll[1]);
        ((__nv_bfloat162*)l)[i*2+1] = __nv_bfloat162(ll[2], ll[3]);
    } else if (id < NXB + NPB + NTB) {
        int idx2 = id - NXB - NPB;
        int job = idx2 / 768, idx = idx2 % 768;
        const float* src; __nv_bfloat16 *dh, *dl;
        int R, C, c0, r0;
        if (job < 3) {
            src = (job == 0) ? Wq : (job == 1) ? Wk : Wv;
            dh = g_wh + (long)job*512*1536; dl = g_wl + (long)job*512*1536;
            R = 1536; C = 512;
            c0 = (idx & 15)*32; r0 = (idx >> 4)*32;
        } else if (job == 3) {
            src = Wo; dh = g_woh; dl = g_wol;
            R = 512; C = 1536;
            c0 = (idx % 48)*32; r0 = (idx / 48)*32;
        } else {
            if (idx >= 96) return;
            src = Wrel; dh = g_wrh; dl = g_wrl;
            R = 192; C = 512;
            c0 = (idx & 15)*32; r0 = (idx >> 4)*32;
        }
        int tx = tid & 31, ty = tid >> 5;
        #pragma unroll
        for (int i = 0; i < 4; i++)
            t[ty + i*8][tx] = src[(long)(r0 + ty + i*8)*C + c0 + tx];
        __syncthreads();
        #pragma unroll
        for (int i = 0; i < 4; i++) {
            int c = c0 + ty + i*8, r = r0 + tx;
            float v = t[tx][ty + i*8];
            __nv_bfloat16 hv = __float2bfloat16(v);
            dh[(long)c*R + r] = hv;
            dl[(long)c*R + r] = __float2bfloat16(v - __bfloat162float(hv));
        }
    } else {
        int tb = id - NXB - NPB - NTB;
        int g  = tid >> 6;
        int r  = tid & 63;
        int w  = tid >> 5;
        int lane = tid & 31;
        int tt = tb*4 + g;
        int jt = tt % QT_;
        int qt = (tt / QT_) % QT_;
        int b  = tt / (QT_*QT_);
        int i0 = qt*64, j0 = jt*64;
        unsigned int w0 = *(const unsigned int*)lm;
        int mt;
        if ((w0 & 0xFFu) == 1u && ((w0 >> 8) & 0xFFu) == 1u) mt = 0;
        else if (w0 == 1u) mt = 1;
        else mt = 2;

        bool cpred = rd_mask(isg, (long)b*N_ + j0 + r, mt);
        unsigned int cw = __ballot_sync(0xffffffffu, cpred);
        if (lane == 0) cg[w] = cw;

        bool rg = rd_mask(isg, (long)b*N_ + i0 + r, mt);

        unsigned long long rowbits = 0ull;
        if (mt == 0) {
            const uint4* rp = (const uint4*)(lm + (long)(i0 + r)*N_ + j0);
            #pragma unroll
            for (int q = 0; q < 4; q++) {
                uint4 v = rp[q];
                unsigned int ws[4] = {v.x, v.y, v.z, v.w};
                #pragma unroll
                for (int k = 0; k < 4; k++) {
                    unsigned int nz  = __vcmpne4(ws[k], 0u) & 0x01010101u;
                    unsigned int nib = (nz * 0x01020408u) >> 24;
                    rowbits |= (unsigned long long)(nib & 0xFu) << (q*16 + k*4);
                }
            }
        } else {
            for (int c = 0; c < 64; c++)
                rowbits |= (unsigned long long)(rd_mask(lm, (long)(i0+r)*N_ + j0 + c, mt) ? 1 : 0) << c;
        }
        __syncthreads();
        unsigned long long colbits = (unsigned long long)cg[g*2]
                                   | ((unsigned long long)cg[g*2+1] << 32);
        unsigned long long bits = rg ? ~0ull : (rowbits | colbits);
        g_mbits[(long)tt*64 + r] = bits;
        unsigned int anyw = __ballot_sync(0xffffffffu, bits != 0ull);
        if (lane == 0) anyA[w] = anyw ? 1 : 0;
        __syncthreads();
        if (r == 0) g_tact[tt] = (unsigned char)(anyA[g*2] | anyA[g*2+1]);
    }
}

// ---------------- warp-MMA bf16 split-precision GEMM (3-stage, swizzled) ----------------
#define TBYTES 8192              // 128 rows x 64 B
#define STAGE  (4*TBYTES)        // 32768
#define NSTG   3
#define WG_SMEM (NSTG*STAGE)     // 98304

__global__ __launch_bounds__(256, 2)
void wmma_gemm(const __nv_bfloat16* __restrict__ Ah, const __nv_bfloat16* __restrict__ Al,
               const __nv_bfloat16* __restrict__ Bh, const __nv_bfloat16* __restrict__ Bl,
               const float* __restrict__ bias, const float* __restrict__ bias2,
               float* __restrict__ Cout, int K, int mode)
{
    extern __shared__ char smem[];
    const uint32_t sb = smem_to_u32(smem);
    const int tid = threadIdx.x;
    const int lane = tid & 31;
    const int wid = tid >> 5;
    const int warp_m = wid >> 2;
    const int warp_n = wid & 3;
    const int grp = lane >> 2;
    const int tig = lane & 3;

    int m0, n0, Keff = K, mode_eff = mode;
    const char* srcs[4];
    if (mode == 0) {
        int id = blockIdx.x;
        if (id < 288) {
            m0 = (id % 24) * 128; n0 = (id / 24) * 128;
            srcs[0] = (const char*)Ah; srcs[1] = (const char*)Al;
            srcs[2] = (const char*)Bh; srcs[3] = (const char*)Bl;
        } else {
            id -= 288;
            m0 = (id % 24) * 128; n0 = (id / 24) * 128;
            srcs[0] = (const char*)g_ph;  srcs[1] = (const char*)g_pl;
            srcs[2] = (const char*)g_wrh; srcs[3] = (const char*)g_wrl;
            Keff = 192; mode_eff = 2;
        }
    } else {
        m0 = blockIdx.x * 128; n0 = blockIdx.y * 128;
        srcs[0] = (const char*)Ah; srcs[1] = (const char*)Al;
        srcs[2] = (const char*)Bh; srcs[3] = (const char*)Bl;
    }

    const int arow_l = lane & 15;
    const int achk_l = lane >> 4;
    const int brow_l = ((lane >> 4) << 3) + (lane & 7);
    const int bchk_l = (lane >> 3) & 1;

    const int rb[4] = {m0, m0, n0, n0};
    const long rowB = (long)Keff * 2;

    auto issue_stage = [&](int kt, int st) {
        const uint32_t sbase = sb + st*STAGE;
        #pragma unroll
        for (int l = 0; l < 8; l++) {
            int i = tid + l*256;
            int t = i >> 9, r = (i >> 2) & 127, c = i & 3;
            const char* g = srcs[t] + (long)(rb[t] + r)*rowB + kt*64 + c*16;
            cp_async16(swz(sbase + t*TBYTES, r, c), g);
        }
        CP_COMMIT();
    };

    float acc[4][4][4];
    #pragma unroll
    for (int i = 0; i < 4; i++)
        #pragma unroll
        for (int j = 0; j < 4; j++)
            #pragma unroll
            for (int e = 0; e < 4; e++) acc[i][j][e] = 0.f;

    const int nk = Keff / 32;
    issue_stage(0, 0);
    issue_stage(1, 1);

    for (int kt = 0; kt < nk; kt++) {
        CP_WAIT1();
        __syncthreads();
        if (kt + 2 < nk) issue_stage(kt + 2, (kt + 2) % NSTG);

        const uint32_t stg = sb + (kt % NSTG)*STAGE;
        const uint32_t aoffh = stg + 0*TBYTES;
        const uint32_t aoffl = stg + 1*TBYTES;
        const uint32_t boffh = stg + 2*TBYTES;
        const uint32_t boffl = stg + 3*TBYTES;

        #pragma unroll
        for (int ks = 0; ks < 2; ks++) {
            uint32_t bh[4][2], bl[4][2];
            #pragma unroll
            for (int jp = 0; jp < 2; jp++) {
                int brw = warp_n*32 + jp*16 + brow_l;
                int bck = ks*2 + bchk_l;
                uint32_t r4[4];
                ldsm_x4(r4, swz(boffh, brw, bck));
                bh[2*jp][0] = r4[0]; bh[2*jp][1] = r4[1];
                bh[2*jp+1][0] = r4[2]; bh[2*jp+1][1] = r4[3];
                ldsm_x4(r4, swz(boffl, brw, bck));
                bl[2*jp][0] = r4[0]; bl[2*jp][1] = r4[1];
                bl[2*jp+1][0] = r4[2]; bl[2*jp+1][1] = r4[3];
            }
            #pragma unroll
            for (int i = 0; i < 4; i++) {
                int arw = warp_m*64 + i*16 + arow_l;
                int ack = ks*2 + achk_l;
                uint32_t ah[4], al[4];
                ldsm_x4(ah, swz(aoffh, arw, ack));
                ldsm_x4(al, swz(aoffl, arw, ack));
                #pragma unroll
                for (int j = 0; j < 4; j++) mma_bf16(acc[i][j], ah, bh[j]);
                #pragma unroll
                for (int j = 0; j < 4; j++) mma_bf16(acc[i][j], ah, bl[j]);
                #pragma unroll
                for (int j = 0; j < 4; j++) mma_bf16(acc[i][j], al, bh[j]);
            }
        }
    }

    // epilogue
    #pragma unroll
    for (int i = 0; i < 4; i++) {
        #pragma unroll
        for (int j = 0; j < 4; j++) {
            const int r0 = m0 + warp_m*64 + i*16 + grp;
            const int c0 = n0 + warp_n*32 + j*8 + 2*tig;
            #pragma unroll
            for (int half = 0; half < 2; half++) {
                const int row = r0 + half*8;
                float v0 = acc[i][j][half*2 + 0];
                float v1 = acc[i][j][half*2 + 1];
                if (mode_eff == 1) {
                    Cout[(long)row*1536 + c0]     = v0 + bias[c0];
                    Cout[(long)row*1536 + c0 + 1] = v1 + bias[c0 + 1];
                } else if (mode_eff == 2) {
                    const int h = c0 >> 6, d = c0 & 63;
                    uint32_t hi, lo; split2(v0, v1, hi, lo);
                    long idx = ((long)h*RP_ + row)*D_ + d;
                    *(uint32_t*)&g_rh[idx] = hi;
                    *(uint32_t*)&g_rl[idx] = lo;
                } else {
                    const int sel = c0 >> 9, pc = c0 & 511;
                    const int h = pc >> 6, d = pc & 63;
                    const int bb = (row >= N_) ? 1 : 0;
                    const int ii = row - bb*N_;
                    const int bhd = bb*H_ + h;
                    if (sel == 0) {
                        float s0 = v0*0.125f, s1 = v1*0.125f;
                        long idx = ((long)bhd*N_ + ii)*D_ + d;
                        uint32_t hi, lo;
                        split2(s0 + bias[pc], s1 + bias[pc + 1], hi, lo);
                        *(uint32_t*)&g_qh[idx] = hi;
                        *(uint32_t*)&g_ql[idx] = lo;
                        split2(s0 + bias2[pc], s1 + bias2[pc + 1], hi, lo);
                        *(uint32_t*)&g_qph[idx] = hi;
                        *(uint32_t*)&g_qpl[idx] = lo;
                    } else if (sel == 1) {
                        uint32_t hi, lo; split2(v0, v1, hi, lo);
                        long idx = ((long)bhd*N_ + ii)*D_ + d;
                        *(uint32_t*)&g_kh[idx] = hi;
                        *(uint32_t*)&g_kl[idx] = lo;
                    } else {
                        __nv_bfloat16 h0 = __float2bfloat16(v0);
                        __nv_bfloat16 h1 = __float2bfloat16(v1);
                        long i0x = ((long)bhd*D_ + d)*N_ + ii;
                        long i1x = ((long)bhd*D_ + d + 1)*N_ + ii;
                        g_vth[i0x] = h0;
                        g_vth[i1x] = h1;
                        g_vtl[i0x] = __float2bfloat16(v0 - __bfloat162float(h0));
                        g_vtl[i1x] = __float2bfloat16(v1 - __bfloat162float(h1));
                    }
                }
            }
        }
    }
}

// ---------------- mma.sync flash attention (ldmatrix, banded G) ----------------
#define AK_H   0u
#define AK_L   9216u
#define AVT_H  18432u
#define AVT_L  27648u
#define AR_H   36864u
#define AR_L   55296u
#define AG     73728u
#define ATTN2_SMEM (73728 + 64*132*4)

__global__ __launch_bounds__(128, 2)
void attn_mma()
{
    extern __shared__ char sm2[];
    const uint32_t sb = smem_to_u32(sm2);
    float* sG = (float*)(sm2 + AG);

    const int tid = threadIdx.x;
    const int lane = tid & 31;
    const int w = tid >> 5;
    const int grp = lane >> 2;
    const int tig = lane & 3;
    const int qt = blockIdx.x;
    const int bh = blockIdx.y;
    const int b = bh >> 3, h = bh & 7;
    const int i0 = qt * 64;

    const int brow_l = ((lane >> 4) << 3) + (lane & 7);
    const int bcol_l = ((lane >> 3) & 1) * 16;

    // G-band block window for this warp: rows [16w,16w+15] need cols [48-16w,126-16w]
    // -> 16-col blocks gb in [3-w, 7-w]
    const int gb_lo = 3 - w;
    const int gb_hi = 7 - w;

    // ---- Q fragments (persistent): content (cb) + positional (pb) ----
    const __nv_bfloat16* qbh = g_qh  + (long)bh*N_*D_;
    const __nv_bfloat16* qbl = g_ql  + (long)bh*N_*D_;
    const __nv_bfloat16* pqh = g_qph + (long)bh*N_*D_;
    const __nv_bfloat16* pql = g_qpl + (long)bh*N_*D_;
    const int rq0 = i0 + w*16 + grp, rq1 = rq0 + 8;
    uint32_t qfh[4][4], qfl[4][4], qgh[4][4], qgl[4][4];
    #pragma unroll
    for (int kf = 0; kf < 4; kf++) {
        qfh[kf][0] = *(const uint32_t*)(qbh + (long)rq0*D_ + kf*16 + 2*tig);
        qfh[kf][1] = *(const uint32_t*)(qbh + (long)rq1*D_ + kf*16 + 2*tig);
        qfh[kf][2] = *(const uint32_t*)(qbh + (long)rq0*D_ + kf*16 + 8 + 2*tig);
        qfh[kf][3] = *(const uint32_t*)(qbh + (long)rq1*D_ + kf*16 + 8 + 2*tig);
        qfl[kf][0] = *(const uint32_t*)(qbl + (long)rq0*D_ + kf*16 + 2*tig);
        qfl[kf][1] = *(const uint32_t*)(qbl + (long)rq1*D_ + kf*16 + 2*tig);
        qfl[kf][2] = *(const uint32_t*)(qbl + (long)rq0*D_ + kf*16 + 8 + 2*tig);
        qfl[kf][3] = *(const uint32_t*)(qbl + (long)rq1*D_ + kf*16 + 8 + 2*tig);
        qgh[kf][0] = *(const uint32_t*)(pqh + (long)rq0*D_ + kf*16 + 2*tig);
        qgh[kf][1] = *(const uint32_t*)(pqh + (long)rq1*D_ + kf*16 + 2*tig);
        qgh[kf][2] = *(const uint32_t*)(pqh + (long)rq0*D_ + kf*16 + 8 + 2*tig);
        qgh[kf][3] = *(const uint32_t*)(pqh + (long)rq1*D_ + kf*16 + 8 + 2*tig);
        qgl[kf][0] = *(const uint32_t*)(pql + (long)rq0*D_ + kf*16 + 2*tig);
        qgl[kf][1] = *(const uint32_t*)(pql + (long)rq1*D_ + kf*16 + 2*tig);
        qgl[kf][2] = *(const uint32_t*)(pql + (long)rq0*D_ + kf*16 + 8 + 2*tig);
        qgl[kf][3] = *(const uint32_t*)(pql + (long)rq1*D_ + kf*16 + 8 + 2*tig);
    }

    float o[8][4];
    #pragma unroll
    for (int nf = 0; nf < 8; nf++)
        #pragma unroll
        for (int e = 0; e < 4; e++) o[nf][e] = 0.f;
    float mrow[2] = {-1e30f, -1e30f};
    float lrow[2] = {0.f, 0.f};

    const unsigned char* tact = &g_tact[(b*QT_ + qt)*QT_];
    const long kbase  = (long)bh*N_*D_;
    const long vbase  = (long)bh*D_*N_;
    const long rbase  = (long)h*RP_*D_;

    for (int jt = 0; jt < QT_; jt++) {
        if (!tact[jt]) continue;
        const int j0 = jt*64;
        const int p0 = j0 - i0 + (N_ - 1) - 63;

        __syncthreads();
        #pragma unroll
        for (int l = 0; l < 4; l++) {
            int i = tid + l*128;
            int r = i >> 3, c = i & 7;
            long krow = (kbase + (long)(j0 + r)*D_)*2;
            long vrow = (vbase + (long)r*N_ + j0)*2;
            cp_async16(sb + AK_H  + r*144 + c*16, (const char*)g_kh  + krow + c*16);
            cp_async16(sb + AK_L  + r*144 + c*16, (const char*)g_kl  + krow + c*16);
            cp_async16(sb + AVT_H + r*144 + c*16, (const char*)g_vth + vrow + c*16);
            cp_async16(sb + AVT_L + r*144 + c*16, (const char*)g_vtl + vrow + c*16);
        }
        #pragma unroll
        for (int l = 0; l < 8; l++) {
            int i = tid + l*128;
            int r = i >> 3, c = i & 7;
            long rrow = (rbase + (long)(p0 + r)*D_)*2;
            cp_async16(sb + AR_H + r*144 + c*16, (const char*)g_rh + rrow + c*16);
            cp_async16(sb + AR_L + r*144 + c*16, (const char*)g_rl + rrow + c*16);
        }
        CP_COMMIT();

        const unsigned long long* mb = g_mbits + ((long)(b*QT_ + qt)*QT_ + jt)*64;
        unsigned long long mw0 = mb[w*16 + grp];
        unsigned long long mw1 = mb[w*16 + grp + 8];

        CP_WAIT0();
        __syncthreads();

        // ---- content logits: Qc @ K^T ----
        float ca[8][4];
        #pragma unroll
        for (int nf = 0; nf < 8; nf++)
            #pragma unroll
            for (int e = 0; e < 4; e++) ca[nf][e] = 0.f;
        #pragma unroll
        for (int kf = 0; kf < 4; kf++) {
            #pragma unroll
            for (int np = 0; np < 4; np++) {
                uint32_t ro = (uint32_t)(np*16 + brow_l)*144 + kf*32 + bcol_l;
                uint32_t kh4[4], kl4[4];
                ldsm_x4(kh4, sb + AK_H + ro);
                ldsm_x4(kl4, sb + AK_L + ro);
                mma_bf16(ca[2*np],   qfh[kf], &kh4[0]);
                mma_bf16(ca[2*np+1], qfh[kf], &kh4[2]);
                mma_bf16(ca[2*np],   qfh[kf], &kl4[0]);
                mma_bf16(ca[2*np+1], qfh[kf], &kl4[2]);
                mma_bf16(ca[2*np],   qfl[kf], &kh4[0]);
                mma_bf16(ca[2*np+1], qfl[kf], &kh4[2]);
            }
        }

        // ---- G = Qp @ Rband^T : only the 5 column-blocks this warp gathers ----
        const int grow = w*16 + grp;
        #pragma unroll
        for (int gh = 0; gh < 2; gh++) {
            #pragma unroll
            for (int np = 0; np < 4; np++) {
                const int gb = gh*4 + np;
                if (gb < gb_lo || gb > gb_hi) continue;   // warp-uniform skip
                float ga0[4] = {0.f, 0.f, 0.f, 0.f};
                float ga1[4] = {0.f, 0.f, 0.f, 0.f};
                #pragma unroll
                for (int kf = 0; kf < 4; kf++) {
                    uint32_t ro = (uint32_t)(gb*16 + brow_l)*144 + kf*32 + bcol_l;
                    uint32_t rh4[4], rl4[4];
                    ldsm_x4(rh4, sb + AR_H + ro);
                    ldsm_x4(rl4, sb + AR_L + ro);
                    mma_bf16(ga0, qgh[kf], &rh4[0]);
                    mma_bf16(ga1, qgh[kf], &rh4[2]);
                    mma_bf16(ga0, qgh[kf], &rl4[0]);
                    mma_bf16(ga1, qgh[kf], &rl4[2]);
                    mma_bf16(ga0, qgl[kf], &rh4[0]);
                    mma_bf16(ga1, qgl[kf], &rh4[2]);
                }
                int col = gb*16 + 2*tig;
                sG[grow*132 + col]            = ga0[0];
                sG[grow*132 + col + 1]        = ga0[1];
                sG[(grow + 8)*132 + col]      = ga0[2];
                sG[(grow + 8)*132 + col + 1]  = ga0[3];
                sG[grow*132 + col + 8]        = ga1[0];
                sG[grow*132 + col + 9]        = ga1[1];
                sG[(grow + 8)*132 + col + 8]  = ga1[2];
                sG[(grow + 8)*132 + col + 9]  = ga1[3];
            }
        }
        __syncwarp();

        // ---- gather + mask + online softmax ----
        float pv0[16], pv1[16];
        #pragma unroll
        for (int h2 = 0; h2 < 2; h2++) {
            const int rl = grow + 8*h2;
            const unsigned long long mw = h2 ? mw1 : mw0;
            float* pvv = h2 ? pv1 : pv0;
            float lg[16];
            float tmax = -1e30f;
            #pragma unroll
            for (int nf = 0; nf < 8; nf++) {
                #pragma unroll
                for (int e = 0; e < 2; e++) {
                    int c = 8*nf + 2*tig + e;
                    int pp = c - rl + 63;
                    float val = ca[nf][2*h2 + e] + sG[rl*132 + pp];
                    bool act = (mw >> c) & 1ull;
                    float lv = act ? val : -1e30f;
                    lg[nf*2 + e] = lv;
                    tmax = fmaxf(tmax, lv);
                }
            }
            tmax = fmaxf(tmax, __shfl_xor_sync(0xffffffffu, tmax, 1));
            tmax = fmaxf(tmax, __shfl_xor_sync(0xffffffffu, tmax, 2));
            float nm = fmaxf(mrow[h2], tmax);
            float corr = __expf(mrow[h2] - nm);
            mrow[h2] = nm;
            float ps = 0.f;
            #pragma unroll
            for (int e2 = 0; e2 < 16; e2++) {
                float p = (lg[e2] <= -1e29f) ? 0.f : __expf(lg[e2] - nm);
                pvv[e2] = p;
                ps += p;
            }
            ps += __shfl_xor_sync(0xffffffffu, ps, 1);
            ps += __shfl_xor_sync(0xffffffffu, ps, 2);
            lrow[h2] = lrow[h2]*corr + ps;
            #pragma unroll
            for (int nf = 0; nf < 8; nf++) {
                o[nf][2*h2]     *= corr;
                o[nf][2*h2 + 1] *= corr;
            }
        }

        // ---- P fragments ----
        uint32_t pfh[4][4], pfl[4][4];
        #pragma unroll
        for (int kf = 0; kf < 4; kf++) {
            split2(pv0[(2*kf)*2],   pv0[(2*kf)*2+1],   pfh[kf][0], pfl[kf][0]);
            split2(pv1[(2*kf)*2],   pv1[(2*kf)*2+1],   pfh[kf][1], pfl[kf][1]);
            split2(pv0[(2*kf+1)*2], pv0[(2*kf+1)*2+1], pfh[kf][2], pfl[kf][2]);
            split2(pv1[(2*kf+1)*2], pv1[(2*kf+1)*2+1], pfh[kf][3], pfl[kf][3]);
        }

        // ---- PV ----
        #pragma unroll
        for (int kf = 0; kf < 4; kf++) {
            #pragma unroll
            for (int np = 0; np < 4; np++) {
                uint32_t ro = (uint32_t)(np*16 + brow_l)*144 + kf*32 + bcol_l;
                uint32_t vh4[4], vl4[4];
                ldsm_x4(vh4, sb + AVT_H + ro);
                ldsm_x4(vl4, sb + AVT_L + ro);
                mma_bf16(o[2*np],   pfh[kf], &vh4[0]);
                mma_bf16(o[2*np+1], pfh[kf], &vh4[2]);
                mma_bf16(o[2*np],   pfh[kf], &vl4[0]);
                mma_bf16(o[2*np+1], pfh[kf], &vl4[2]);
                mma_bf16(o[2*np],   pfl[kf], &vh4[0]);
                mma_bf16(o[2*np+1], pfl[kf], &vh4[2]);
            }
        }
    }

    // ---- epilogue ----
    #pragma unroll
    for (int h2 = 0; h2 < 2; h2++) {
        float inv = 1.0f / lrow[h2];
        int rl = w*16 + grp + 8*h2;
        long rowbase = ((long)(b*N_ + i0 + rl))*(H_*D_) + h*D_;
        #pragma unroll
        for (int nf = 0; nf < 8; nf++) {
            float f0 = o[nf][2*h2]     * inv;
            float f1 = o[nf][2*h2 + 1] * inv;
            uint32_t hi, lo; split2(f0, f1, hi, lo);
            long idx = rowbase + 8*nf + 2*tig;
            *(uint32_t*)&g_ah[idx] = hi;
            *(uint32_t*)&g_al[idx] = lo;
        }
    }
}

// ---------------- launcher ----------------
extern "C" void kernel_launch(void* const* d_in, const int* in_sizes, int n_in,
                              void* d_out, int out_size)
{
    const float* x    = (const float*)d_in[0];
    const float* Wq   = (const float*)d_in[1];
    const float* Wk   = (const float*)d_in[2];
    const float* Wv   = (const float*)d_in[3];
    const float* Wrel = (const float*)d_in[4];
    const float* cb   = (const float*)d_in[5];
    const float* pb   = (const float*)d_in[6];
    const float* Wo   = (const float*)d_in[7];
    const float* bo   = (const float*)d_in[8];
    const float* pos  = (const float*)d_in[9];
    const unsigned char* lmu = (const unsigned char*)d_in[10];
    const unsigned char* isg = (const unsigned char*)d_in[11];
    float* out = (float*)d_out;

    cudaFuncSetAttribute(wmma_gemm, cudaFuncAttributeMaxDynamicSharedMemorySize, WG_SMEM);
    cudaFuncSetAttribute(attn_mma, cudaFuncAttributeMaxDynamicSharedMemorySize, ATTN2_SMEM);

    __nv_bfloat16 *xh_p, *xl_p, *wh_p, *wl_p, *woh_p, *wol_p, *ah_p, *al_p;
    cudaGetSymbolAddress((void**)&xh_p,  g_xh);
    cudaGetSymbolAddress((void**)&xl_p,  g_xl);
    cudaGetSymbolAddress((void**)&wh_p,  g_wh);
    cudaGetSymbolAddress((void**)&wl_p,  g_wl);
    cudaGetSymbolAddress((void**)&woh_p, g_woh);
    cudaGetSymbolAddress((void**)&wol_p, g_wol);
    cudaGetSymbolAddress((void**)&ah_p,  g_ah);
    cudaGetSymbolAddress((void**)&al_p,  g_al);

    pre_kernel<<<NXB + NPB + NTB + NAB, 256>>>(x, pos, Wq, Wk, Wv, Wo, Wrel,
                                               lmu, isg);                    // 1
    wmma_gemm<<<384, 256, WG_SMEM>>>(xh_p, xl_p, wh_p, wl_p,
                                     cb, pb, nullptr, DIM_, 0);              // 2
    attn_mma<<<dim3(QT_, B_*H_), 128, ATTN2_SMEM>>>();                       // 3
    wmma_gemm<<<dim3(24, 12), 256, WG_SMEM>>>(ah_p, al_p, woh_p, wol_p,
                                              bo, nullptr, out, 512, 1);     // 4
}

// round 14
// speedup vs baseline: 1.2164x; 1.1500x over previous
#include <cuda_runtime.h>
#include <cuda_bf16.h>
#include <math.h>
#include <stdint.h>

#define B_   2
#define N_   1536
#define DIM_ 1536
#define H_   8
#define D_   64
#define P_   3071      // 2N-1
#define RP_  3072      // padded row stride for rel tables
#define QT_  24        // N/64 tiles
#define NSP  4         // splits for qt=0

// ---------------- device scratch (zero-initialized statics) ----------------
__device__ unsigned char g_tact[B_*QT_*QT_];
__device__ unsigned long long g_mbits[B_*QT_*QT_*64];

__device__ float g_po[16*NSP*64*64];   // qt=0 partial o (unnormalized)
__device__ float g_pm[16*NSP*64];      // partial row max
__device__ float g_pl[16*NSP*64];      // partial row sum

__device__ __nv_bfloat16 g_xh[B_*N_*DIM_];
__device__ __nv_bfloat16 g_xl[B_*N_*DIM_];
__device__ __nv_bfloat16 g_ph[RP_*192];
__device__ __nv_bfloat16 g_pl2[RP_*192];
__device__ __nv_bfloat16 g_wh[1536*DIM_];
__device__ __nv_bfloat16 g_wl[1536*DIM_];
__device__ __nv_bfloat16 g_wrh[512*192];
__device__ __nv_bfloat16 g_wrl[512*192];
__device__ __nv_bfloat16 g_woh[1536*512];
__device__ __nv_bfloat16 g_wol[1536*512];
__device__ __nv_bfloat16 g_ah[B_*N_*H_*D_];
__device__ __nv_bfloat16 g_al[B_*N_*H_*D_];
__device__ __nv_bfloat16 g_qh[B_*H_*N_*D_];
__device__ __nv_bfloat16 g_ql[B_*H_*N_*D_];
__device__ __nv_bfloat16 g_qph[B_*H_*N_*D_];
__device__ __nv_bfloat16 g_qpl[B_*H_*N_*D_];
__device__ __nv_bfloat16 g_kh[B_*H_*N_*D_];
__device__ __nv_bfloat16 g_kl[B_*H_*N_*D_];
__device__ __nv_bfloat16 g_vth[B_*H_*D_*N_];
__device__ __nv_bfloat16 g_vtl[B_*H_*D_*N_];
__device__ __nv_bfloat16 g_rh[H_*RP_*D_];
__device__ __nv_bfloat16 g_rl[H_*RP_*D_];

// ---------------- helpers ----------------
__device__ __forceinline__ uint32_t smem_to_u32(const void* p) {
    uint32_t a;
    asm("{ .reg .u64 t; cvta.to.shared.u64 t, %1; cvt.u32.u64 %0, t; }" : "=r"(a) : "l"(p));
    return a;
}
__device__ __forceinline__ void cp_async16(uint32_t saddr, const void* g) {
    asm volatile("cp.async.cg.shared.global [%0], [%1], 16;" :: "r"(saddr), "l"(g));
}
#define CP_COMMIT() asm volatile("cp.async.commit_group;" ::: "memory")
#define CP_WAIT0()  asm volatile("cp.async.wait_group 0;" ::: "memory")
#define CP_WAIT1()  asm volatile("cp.async.wait_group 1;" ::: "memory")

__device__ __forceinline__ void mma_bf16(float* c, const uint32_t* a, const uint32_t* b) {
    asm volatile("mma.sync.aligned.m16n8k16.row.col.f32.bf16.bf16.f32 "
        "{%0,%1,%2,%3}, {%4,%5,%6,%7}, {%8,%9}, {%0,%1,%2,%3};"
        : "+f"(c[0]), "+f"(c[1]), "+f"(c[2]), "+f"(c[3])
        : "r"(a[0]), "r"(a[1]), "r"(a[2]), "r"(a[3]), "r"(b[0]), "r"(b[1]));
}
__device__ __forceinline__ void ldsm_x4(uint32_t* r, uint32_t addr) {
    asm volatile("ldmatrix.sync.aligned.m8n8.x4.shared.b16 {%0,%1,%2,%3}, [%4];"
        : "=r"(r[0]), "=r"(r[1]), "=r"(r[2]), "=r"(r[3]) : "r"(addr));
}
__device__ __forceinline__ void split2(float f0, float f1, uint32_t& hi, uint32_t& lo) {
    __nv_bfloat16 h0 = __float2bfloat16(f0), h1 = __float2bfloat16(f1);
    __nv_bfloat162 hh(h0, h1);
    hi = *(uint32_t*)&hh;
    __nv_bfloat16 l0 = __float2bfloat16(f0 - __bfloat162float(h0));
    __nv_bfloat16 l1 = __float2bfloat16(f1 - __bfloat162float(h1));
    __nv_bfloat162 ll(l0, l1);
    lo = *(uint32_t*)&ll;
}
__device__ __forceinline__ bool rd_mask(const unsigned char* p, long idx, int mt) {
    if (mt == 0) return p[idx] != 0;
    if (mt == 1) return ((const int*)p)[idx] != 0;
    return ((const float*)p)[idx] != 0.0f;
}
__device__ __forceinline__ uint32_t swz(uint32_t base, int r, int c) {
    return base + (uint32_t)r*64u + (uint32_t)((c ^ ((r >> 1) & 3)) << 4);
}

// ---------------- fused pre-processing kernel ----------------
#define NXB 4608
#define NPB 576
#define NTB 3840
#define NAB 288

__global__ void pre_kernel(const float* __restrict__ x, const float* __restrict__ pos,
                           const float* __restrict__ Wq, const float* __restrict__ Wk,
                           const float* __restrict__ Wv, const float* __restrict__ Wo,
                           const float* __restrict__ Wrel,
                           const unsigned char* __restrict__ lm,
                           const unsigned char* __restrict__ isg)
{
    __shared__ float t[32][33];
    __shared__ unsigned int cg[8];
    __shared__ unsigned char anyA[8];
    const int id = blockIdx.x;
    const int tid = threadIdx.x;

    if (id < NXB + NPB) {
        const float* s; __nv_bfloat16 *h, *l; int n4, base;
        if (id < NXB) { s = x; h = g_xh; l = g_xl; n4 = B_*N_*DIM_/4; base = id; }
        else          { s = pos; h = g_ph; l = g_pl2; n4 = P_*192/4; base = id - NXB; }
        int i = base*256 + tid;
        if (i >= n4) return;
        float4 v = ((const float4*)s)[i];
        float a[4] = {v.x, v.y, v.z, v.w};
        __nv_bfloat16 hh[4], ll[4];
        #pragma unroll
        for (int j = 0; j < 4; j++) {
            hh[j] = __float2bfloat16(a[j]);
            ll[j] = __float2bfloat16(a[j] - __bfloat162float(hh[j]));
        }
        ((__nv_bfloat162*)h)[i*2+0] = __nv_bfloat162(hh[0], hh[1]);
        ((__nv_bfloat162*)h)[i*2+1] = __nv_bfloat162(hh[2], hh[3]);
        ((__nv_bfloat162*)l)[i*2+0] = __nv_bfloat162(ll[0], ll[1]);
        ((__nv_bfloat162*)l)[i*2+1] = __nv_bfloat162(ll[2], ll[3]);
    } else if (id < NXB + NPB + NTB) {
        int idx2 = id - NXB - NPB;
        int job = idx2 / 768, idx = idx2 % 768;
        const float* src; __nv_bfloat16 *dh, *dl;
        int R, C, c0, r0;
        if (job < 3) {
            src = (job == 0) ? Wq : (job == 1) ? Wk : Wv;
            dh = g_wh + (long)job*512*1536; dl = g_wl + (long)job*512*1536;
            R = 1536; C = 512;
            c0 = (idx & 15)*32; r0 = (idx >> 4)*32;
        } else if (job == 3) {
            src = Wo; dh = g_woh; dl = g_wol;
            R = 512; C = 1536;
            c0 = (idx % 48)*32; r0 = (idx / 48)*32;
        } else {
            if (idx >= 96) return;
            src = Wrel; dh = g_wrh; dl = g_wrl;
            R = 192; C = 512;
            c0 = (idx & 15)*32; r0 = (idx >> 4)*32;
        }
        int tx = tid & 31, ty = tid >> 5;
        #pragma unroll
        for (int i = 0; i < 4; i++)
            t[ty + i*8][tx] = src[(long)(r0 + ty + i*8)*C + c0 + tx];
        __syncthreads();
        #pragma unroll
        for (int i = 0; i < 4; i++) {
            int c = c0 + ty + i*8, r = r0 + tx;
            float v = t[tx][ty + i*8];
            __nv_bfloat16 hv = __float2bfloat16(v);
            dh[(long)c*R + r] = hv;
            dl[(long)c*R + r] = __float2bfloat16(v - __bfloat162float(hv));
        }
    } else {
        int tb = id - NXB - NPB - NTB;
        int g  = tid >> 6;
        int r  = tid & 63;
        int w  = tid >> 5;
        int lane = tid & 31;
        int tt = tb*4 + g;
        int jt = tt % QT_;
        int qt = (tt / QT_) % QT_;
        int b  = tt / (QT_*QT_);
        int i0 = qt*64, j0 = jt*64;
        unsigned int w0 = *(const unsigned int*)lm;
        int mt;
        if ((w0 & 0xFFu) == 1u && ((w0 >> 8) & 0xFFu) == 1u) mt = 0;
        else if (w0 == 1u) mt = 1;
        else mt = 2;

        bool cpred = rd_mask(isg, (long)b*N_ + j0 + r, mt);
        unsigned int cw = __ballot_sync(0xffffffffu, cpred);
        if (lane == 0) cg[w] = cw;

        bool rg = rd_mask(isg, (long)b*N_ + i0 + r, mt);

        unsigned long long rowbits = 0ull;
        if (mt == 0) {
            const uint4* rp = (const uint4*)(lm + (long)(i0 + r)*N_ + j0);
            #pragma unroll
            for (int q = 0; q < 4; q++) {
                uint4 v = rp[q];
                unsigned int ws[4] = {v.x, v.y, v.z, v.w};
                #pragma unroll
                for (int k = 0; k < 4; k++) {
                    unsigned int nz  = __vcmpne4(ws[k], 0u) & 0x01010101u;
                    unsigned int nib = (nz * 0x01020408u) >> 24;
                    rowbits |= (unsigned long long)(nib & 0xFu) << (q*16 + k*4);
                }
            }
        } else {
            for (int c = 0; c < 64; c++)
                rowbits |= (unsigned long long)(rd_mask(lm, (long)(i0+r)*N_ + j0 + c, mt) ? 1 : 0) << c;
        }
        __syncthreads();
        unsigned long long colbits = (unsigned long long)cg[g*2]
                                   | ((unsigned long long)cg[g*2+1] << 32);
        unsigned long long bits = rg ? ~0ull : (rowbits | colbits);
        g_mbits[(long)tt*64 + r] = bits;
        unsigned int anyw = __ballot_sync(0xffffffffu, bits != 0ull);
        if (lane == 0) anyA[w] = anyw ? 1 : 0;
        __syncthreads();
        if (r == 0) g_tact[tt] = (unsigned char)(anyA[g*2] | anyA[g*2+1]);
    }
}

// ---------------- warp-MMA bf16 split-precision GEMM (3-stage, swizzled) ----------------
#define TBYTES 8192
#define STAGE  (4*TBYTES)
#define NSTG   3
#define WG_SMEM (NSTG*STAGE)

__global__ __launch_bounds__(256, 2)
void wmma_gemm(const __nv_bfloat16* __restrict__ Ah, const __nv_bfloat16* __restrict__ Al,
               const __nv_bfloat16* __restrict__ Bh, const __nv_bfloat16* __restrict__ Bl,
               const float* __restrict__ bias, const float* __restrict__ bias2,
               float* __restrict__ Cout, int K, int mode)
{
    extern __shared__ char smem[];
    const uint32_t sb = smem_to_u32(smem);
    const int tid = threadIdx.x;
    const int lane = tid & 31;
    const int wid = tid >> 5;
    const int warp_m = wid >> 2;
    const int warp_n = wid & 3;
    const int grp = lane >> 2;
    const int tig = lane & 3;

    int m0, n0, Keff = K, mode_eff = mode;
    const char* srcs[4];
    if (mode == 0) {
        int id = blockIdx.x;
        if (id < 288) {
            m0 = (id % 24) * 128; n0 = (id / 24) * 128;
            srcs[0] = (const char*)Ah; srcs[1] = (const char*)Al;
            srcs[2] = (const char*)Bh; srcs[3] = (const char*)Bl;
        } else {
            id -= 288;
            m0 = (id % 24) * 128; n0 = (id / 24) * 128;
            srcs[0] = (const char*)g_ph;  srcs[1] = (const char*)g_pl2;
            srcs[2] = (const char*)g_wrh; srcs[3] = (const char*)g_wrl;
            Keff = 192; mode_eff = 2;
        }
    } else {
        m0 = blockIdx.x * 128; n0 = blockIdx.y * 128;
        srcs[0] = (const char*)Ah; srcs[1] = (const char*)Al;
        srcs[2] = (const char*)Bh; srcs[3] = (const char*)Bl;
    }

    const int arow_l = lane & 15;
    const int achk_l = lane >> 4;
    const int brow_l = ((lane >> 4) << 3) + (lane & 7);
    const int bchk_l = (lane >> 3) & 1;

    const int rb[4] = {m0, m0, n0, n0};
    const long rowB = (long)Keff * 2;

    auto issue_stage = [&](int kt, int st) {
        const uint32_t sbase = sb + st*STAGE;
        #pragma unroll
        for (int l = 0; l < 8; l++) {
            int i = tid + l*256;
            int t = i >> 9, r = (i >> 2) & 127, c = i & 3;
            const char* g = srcs[t] + (long)(rb[t] + r)*rowB + kt*64 + c*16;
            cp_async16(swz(sbase + t*TBYTES, r, c), g);
        }
        CP_COMMIT();
    };

    float acc[4][4][4];
    #pragma unroll
    for (int i = 0; i < 4; i++)
        #pragma unroll
        for (int j = 0; j < 4; j++)
            #pragma unroll
            for (int e = 0; e < 4; e++) acc[i][j][e] = 0.f;

    const int nk = Keff / 32;
    issue_stage(0, 0);
    issue_stage(1, 1);

    for (int kt = 0; kt < nk; kt++) {
        CP_WAIT1();
        __syncthreads();
        if (kt + 2 < nk) issue_stage(kt + 2, (kt + 2) % NSTG);

        const uint32_t stg = sb + (kt % NSTG)*STAGE;
        const uint32_t aoffh = stg + 0*TBYTES;
        const uint32_t aoffl = stg + 1*TBYTES;
        const uint32_t boffh = stg + 2*TBYTES;
        const uint32_t boffl = stg + 3*TBYTES;

        #pragma unroll
        for (int ks = 0; ks < 2; ks++) {
            uint32_t bh[4][2], bl[4][2];
            #pragma unroll
            for (int jp = 0; jp < 2; jp++) {
                int brw = warp_n*32 + jp*16 + brow_l;
                int bck = ks*2 + bchk_l;
                uint32_t r4[4];
                ldsm_x4(r4, swz(boffh, brw, bck));
                bh[2*jp][0] = r4[0]; bh[2*jp][1] = r4[1];
                bh[2*jp+1][0] = r4[2]; bh[2*jp+1][1] = r4[3];
                ldsm_x4(r4, swz(boffl, brw, bck));
                bl[2*jp][0] = r4[0]; bl[2*jp][1] = r4[1];
                bl[2*jp+1][0] = r4[2]; bl[2*jp+1][1] = r4[3];
            }
            #pragma unroll
            for (int i = 0; i < 4; i++) {
                int arw = warp_m*64 + i*16 + arow_l;
                int ack = ks*2 + achk_l;
                uint32_t ah[4], al[4];
                ldsm_x4(ah, swz(aoffh, arw, ack));
                ldsm_x4(al, swz(aoffl, arw, ack));
                #pragma unroll
                for (int j = 0; j < 4; j++) mma_bf16(acc[i][j], ah, bh[j]);
                #pragma unroll
                for (int j = 0; j < 4; j++) mma_bf16(acc[i][j], ah, bl[j]);
                #pragma unroll
                for (int j = 0; j < 4; j++) mma_bf16(acc[i][j], al, bh[j]);
            }
        }
    }

    // epilogue
    #pragma unroll
    for (int i = 0; i < 4; i++) {
        #pragma unroll
        for (int j = 0; j < 4; j++) {
            const int r0 = m0 + warp_m*64 + i*16 + grp;
            const int c0 = n0 + warp_n*32 + j*8 + 2*tig;
            #pragma unroll
            for (int half = 0; half < 2; half++) {
                const int row = r0 + half*8;
                float v0 = acc[i][j][half*2 + 0];
                float v1 = acc[i][j][half*2 + 1];
                if (mode_eff == 1) {
                    Cout[(long)row*1536 + c0]     = v0 + bias[c0];
                    Cout[(long)row*1536 + c0 + 1] = v1 + bias[c0 + 1];
                } else if (mode_eff == 2) {
                    const int h = c0 >> 6, d = c0 & 63;
                    uint32_t hi, lo; split2(v0, v1, hi, lo);
                    long idx = ((long)h*RP_ + row)*D_ + d;
                    *(uint32_t*)&g_rh[idx] = hi;
                    *(uint32_t*)&g_rl[idx] = lo;
                } else {
                    const int sel = c0 >> 9, pc = c0 & 511;
                    const int h = pc >> 6, d = pc & 63;
                    const int bb = (row >= N_) ? 1 : 0;
                    const int ii = row - bb*N_;
                    const int bhd = bb*H_ + h;
                    if (sel == 0) {
                        float s0 = v0*0.125f, s1 = v1*0.125f;
                        long idx = ((long)bhd*N_ + ii)*D_ + d;
                        uint32_t hi, lo;
                        split2(s0 + bias[pc], s1 + bias[pc + 1], hi, lo);
                        *(uint32_t*)&g_qh[idx] = hi;
                        *(uint32_t*)&g_ql[idx] = lo;
                        split2(s0 + bias2[pc], s1 + bias2[pc + 1], hi, lo);
                        *(uint32_t*)&g_qph[idx] = hi;
                        *(uint32_t*)&g_qpl[idx] = lo;
                    } else if (sel == 1) {
                        uint32_t hi, lo; split2(v0, v1, hi, lo);
                        long idx = ((long)bhd*N_ + ii)*D_ + d;
                        *(uint32_t*)&g_kh[idx] = hi;
                        *(uint32_t*)&g_kl[idx] = lo;
                    } else {
                        __nv_bfloat16 h0 = __float2bfloat16(v0);
                        __nv_bfloat16 h1 = __float2bfloat16(v1);
                        long i0x = ((long)bhd*D_ + d)*N_ + ii;
                        long i1x = ((long)bhd*D_ + d + 1)*N_ + ii;
                        g_vth[i0x] = h0;
                        g_vth[i1x] = h1;
                        g_vtl[i0x] = __float2bfloat16(v0 - __bfloat162float(h0));
                        g_vtl[i1x] = __float2bfloat16(v1 - __bfloat162float(h1));
                    }
                }
            }
        }
    }
}

// ---------------- mma.sync flash attention (banded G + split-KV for qt=0) ----------------
#define AK_H   0u
#define AK_L   9216u
#define AVT_H  18432u
#define AVT_L  27648u
#define AR_H   36864u
#define AR_L   55296u
#define AG     73728u
#define ATTN2_SMEM (73728 + 64*132*4)

__global__ __launch_bounds__(128, 2)
void attn_mma()
{
    extern __shared__ char sm2[];
    const uint32_t sb = smem_to_u32(sm2);
    float* sG = (float*)(sm2 + AG);

    const int tid = threadIdx.x;
    const int lane = tid & 31;
    const int w = tid >> 5;
    const int grp = lane >> 2;
    const int tig = lane & 3;
    const int qs = blockIdx.x;          // 0..26
    const int bh = blockIdx.y;
    const int b = bh >> 3, h = bh & 7;

    int qt, sp, jt_lo, jt_hi;
    if (qs < 24) { qt = qs; sp = 0; } else { qt = 0; sp = qs - 23; }
    if (qt == 0) { jt_lo = sp*6; jt_hi = jt_lo + 6; }
    else         { jt_lo = 0; jt_hi = QT_; }
    const int i0 = qt * 64;

    const int brow_l = ((lane >> 4) << 3) + (lane & 7);
    const int bcol_l = ((lane >> 3) & 1) * 16;
    const int gb_lo = 3 - w;
    const int gb_hi = 7 - w;

    const __nv_bfloat16* qbh = g_qh  + (long)bh*N_*D_;
    const __nv_bfloat16* qbl = g_ql  + (long)bh*N_*D_;
    const __nv_bfloat16* pqh = g_qph + (long)bh*N_*D_;
    const __nv_bfloat16* pql = g_qpl + (long)bh*N_*D_;
    const int rq0 = i0 + w*16 + grp, rq1 = rq0 + 8;
    uint32_t qfh[4][4], qfl[4][4], qgh[4][4], qgl[4][4];
    #pragma unroll
    for (int kf = 0; kf < 4; kf++) {
        qfh[kf][0] = *(const uint32_t*)(qbh + (long)rq0*D_ + kf*16 + 2*tig);
        qfh[kf][1] = *(const uint32_t*)(qbh + (long)rq1*D_ + kf*16 + 2*tig);
        qfh[kf][2] = *(const uint32_t*)(qbh + (long)rq0*D_ + kf*16 + 8 + 2*tig);
        qfh[kf][3] = *(const uint32_t*)(qbh + (long)rq1*D_ + kf*16 + 8 + 2*tig);
        qfl[kf][0] = *(const uint32_t*)(qbl + (long)rq0*D_ + kf*16 + 2*tig);
        qfl[kf][1] = *(const uint32_t*)(qbl + (long)rq1*D_ + kf*16 + 2*tig);
        qfl[kf][2] = *(const uint32_t*)(qbl + (long)rq0*D_ + kf*16 + 8 + 2*tig);
        qfl[kf][3] = *(const uint32_t*)(qbl + (long)rq1*D_ + kf*16 + 8 + 2*tig);
        qgh[kf][0] = *(const uint32_t*)(pqh + (long)rq0*D_ + kf*16 + 2*tig);
        qgh[kf][1] = *(const uint32_t*)(pqh + (long)rq1*D_ + kf*16 + 2*tig);
        qgh[kf][2] = *(const uint32_t*)(pqh + (long)rq0*D_ + kf*16 + 8 + 2*tig);
        qgh[kf][3] = *(const uint32_t*)(pqh + (long)rq1*D_ + kf*16 + 8 + 2*tig);
        qgl[kf][0] = *(const uint32_t*)(pql + (long)rq0*D_ + kf*16 + 2*tig);
        qgl[kf][1] = *(const uint32_t*)(pql + (long)rq1*D_ + kf*16 + 2*tig);
        qgl[kf][2] = *(const uint32_t*)(pql + (long)rq0*D_ + kf*16 + 8 + 2*tig);
        qgl[kf][3] = *(const uint32_t*)(pql + (long)rq1*D_ + kf*16 + 8 + 2*tig);
    }

    float o[8][4];
    #pragma unroll
    for (int nf = 0; nf < 8; nf++)
        #pragma unroll
        for (int e = 0; e < 4; e++) o[nf][e] = 0.f;
    float mrow[2] = {-1e30f, -1e30f};
    float lrow[2] = {0.f, 0.f};

    const unsigned char* tact = &g_tact[(b*QT_ + qt)*QT_];
    const long kbase  = (long)bh*N_*D_;
    const long vbase  = (long)bh*D_*N_;
    const long rbase  = (long)h*RP_*D_;

    for (int jt = jt_lo; jt < jt_hi; jt++) {
        if (!tact[jt]) continue;
        const int j0 = jt*64;
        const int p0 = j0 - i0 + (N_ - 1) - 63;

        __syncthreads();
        #pragma unroll
        for (int l = 0; l < 4; l++) {
            int i = tid + l*128;
            int r = i >> 3, c = i & 7;
            long krow = (kbase + (long)(j0 + r)*D_)*2;
            long vrow = (vbase + (long)r*N_ + j0)*2;
            cp_async16(sb + AK_H  + r*144 + c*16, (const char*)g_kh  + krow + c*16);
            cp_async16(sb + AK_L  + r*144 + c*16, (const char*)g_kl  + krow + c*16);
            cp_async16(sb + AVT_H + r*144 + c*16, (const char*)g_vth + vrow + c*16);
            cp_async16(sb + AVT_L + r*144 + c*16, (const char*)g_vtl + vrow + c*16);
        }
        #pragma unroll
        for (int l = 0; l < 8; l++) {
            int i = tid + l*128;
            int r = i >> 3, c = i & 7;
            long rrow = (rbase + (long)(p0 + r)*D_)*2;
            cp_async16(sb + AR_H + r*144 + c*16, (const char*)g_rh + rrow + c*16);
            cp_async16(sb + AR_L + r*144 + c*16, (const char*)g_rl + rrow + c*16);
        }
        CP_COMMIT();

        const unsigned long long* mb = g_mbits + ((long)(b*QT_ + qt)*QT_ + jt)*64;
        unsigned long long mw0 = mb[w*16 + grp];
        unsigned long long mw1 = mb[w*16 + grp + 8];

        CP_WAIT0();
        __syncthreads();

        float ca[8][4];
        #pragma unroll
        for (int nf = 0; nf < 8; nf++)
            #pragma unroll
            for (int e = 0; e < 4; e++) ca[nf][e] = 0.f;
        #pragma unroll
        for (int kf = 0; kf < 4; kf++) {
            #pragma unroll
            for (int np = 0; np < 4; np++) {
                uint32_t ro = (uint32_t)(np*16 + brow_l)*144 + kf*32 + bcol_l;
                uint32_t kh4[4], kl4[4];
                ldsm_x4(kh4, sb + AK_H + ro);
                ldsm_x4(kl4, sb + AK_L + ro);
                mma_bf16(ca[2*np],   qfh[kf], &kh4[0]);
                mma_bf16(ca[2*np+1], qfh[kf], &kh4[2]);
                mma_bf16(ca[2*np],   qfh[kf], &kl4[0]);
                mma_bf16(ca[2*np+1], qfh[kf], &kl4[2]);
                mma_bf16(ca[2*np],   qfl[kf], &kh4[0]);
                mma_bf16(ca[2*np+1], qfl[kf], &kh4[2]);
            }
        }

        const int grow = w*16 + grp;
        #pragma unroll
        for (int gh = 0; gh < 2; gh++) {
            #pragma unroll
            for (int np = 0; np < 4; np++) {
                const int gb = gh*4 + np;
                if (gb < gb_lo || gb > gb_hi) continue;
                float ga0[4] = {0.f, 0.f, 0.f, 0.f};
                float ga1[4] = {0.f, 0.f, 0.f, 0.f};
                #pragma unroll
                for (int kf = 0; kf < 4; kf++) {
                    uint32_t ro = (uint32_t)(gb*16 + brow_l)*144 + kf*32 + bcol_l;
                    uint32_t rh4[4], rl4[4];
                    ldsm_x4(rh4, sb + AR_H + ro);
                    ldsm_x4(rl4, sb + AR_L + ro);
                    mma_bf16(ga0, qgh[kf], &rh4[0]);
                    mma_bf16(ga1, qgh[kf], &rh4[2]);
                    mma_bf16(ga0, qgh[kf], &rl4[0]);
                    mma_bf16(ga1, qgh[kf], &rl4[2]);
                    mma_bf16(ga0, qgl[kf], &rh4[0]);
                    mma_bf16(ga1, qgl[kf], &rh4[2]);
                }
                int col = gb*16 + 2*tig;
                sG[grow*132 + col]            = ga0[0];
                sG[grow*132 + col + 1]        = ga0[1];
                sG[(grow + 8)*132 + col]      = ga0[2];
                sG[(grow + 8)*132 + col + 1]  = ga0[3];
                sG[grow*132 + col + 8]        = ga1[0];
                sG[grow*132 + col + 9]        = ga1[1];
                sG[(grow + 8)*132 + col + 8]  = ga1[2];
                sG[(grow + 8)*132 + col + 9]  = ga1[3];
            }
        }
        __syncwarp();

        float pv0[16], pv1[16];
        #pragma unroll
        for (int h2 = 0; h2 < 2; h2++) {
            const int rl = grow + 8*h2;
            const unsigned long long mw = h2 ? mw1 : mw0;
            float* pvv = h2 ? pv1 : pv0;
            float lg[16];
            float tmax = -1e30f;
            #pragma unroll
            for (int nf = 0; nf < 8; nf++) {
                #pragma unroll
                for (int e = 0; e < 2; e++) {
                    int c = 8*nf + 2*tig + e;
                    int pp = c - rl + 63;
                    float val = ca[nf][2*h2 + e] + sG[rl*132 + pp];
                    bool act = (mw >> c) & 1ull;
                    float lv = act ? val : -1e30f;
                    lg[nf*2 + e] = lv;
                    tmax = fmaxf(tmax, lv);
                }
            }
            tmax = fmaxf(tmax, __shfl_xor_sync(0xffffffffu, tmax, 1));
            tmax = fmaxf(tmax, __shfl_xor_sync(0xffffffffu, tmax, 2));
            float nm = fmaxf(mrow[h2], tmax);
            float corr = __expf(mrow[h2] - nm);
            mrow[h2] = nm;
            float ps = 0.f;
            #pragma unroll
            for (int e2 = 0; e2 < 16; e2++) {
                float p = (lg[e2] <= -1e29f) ? 0.f : __expf(lg[e2] - nm);
                pvv[e2] = p;
                ps += p;
            }
            ps += __shfl_xor_sync(0xffffffffu, ps, 1);
            ps += __shfl_xor_sync(0xffffffffu, ps, 2);
            lrow[h2] = lrow[h2]*corr + ps;
            #pragma unroll
            for (int nf = 0; nf < 8; nf++) {
                o[nf][2*h2]     *= corr;
                o[nf][2*h2 + 1] *= corr;
            }
        }

        uint32_t pfh[4][4], pfl[4][4];
        #pragma unroll
        for (int kf = 0; kf < 4; kf++) {
            split2(pv0[(2*kf)*2],   pv0[(2*kf)*2+1],   pfh[kf][0], pfl[kf][0]);
            split2(pv1[(2*kf)*2],   pv1[(2*kf)*2+1],   pfh[kf][1], pfl[kf][1]);
            split2(pv0[(2*kf+1)*2], pv0[(2*kf+1)*2+1], pfh[kf][2], pfl[kf][2]);
            split2(pv1[(2*kf+1)*2], pv1[(2*kf+1)*2+1], pfh[kf][3], pfl[kf][3]);
        }

        #pragma unroll
        for (int kf = 0; kf < 4; kf++) {
            #pragma unroll
            for (int np = 0; np < 4; np++) {
                uint32_t ro = (uint32_t)(np*16 + brow_l)*144 + kf*32 + bcol_l;
                uint32_t vh4[4], vl4[4];
                ldsm_x4(vh4, sb + AVT_H + ro);
                ldsm_x4(vl4, sb + AVT_L + ro);
                mma_bf16(o[2*np],   pfh[kf], &vh4[0]);
                mma_bf16(o[2*np+1], pfh[kf], &vh4[2]);
                mma_bf16(o[2*np],   pfh[kf], &vl4[0]);
                mma_bf16(o[2*np+1], pfh[kf], &vl4[2]);
                mma_bf16(o[2*np],   pfl[kf], &vh4[0]);
                mma_bf16(o[2*np+1], pfl[kf], &vh4[2]);
            }
        }
    }

    // ---- epilogue ----
    if (qt == 0) {
        // partial store (unnormalized) for split-KV merge
        const long pbase = ((long)bh*NSP + sp)*64*64;
        #pragma unroll
        for (int h2 = 0; h2 < 2; h2++) {
            int rl = w*16 + grp + 8*h2;
            if (tig == 0) {
                g_pm[((long)bh*NSP + sp)*64 + rl] = mrow[h2];
                g_pl[((long)bh*NSP + sp)*64 + rl] = lrow[h2];
            }
            #pragma unroll
            for (int nf = 0; nf < 8; nf++) {
                g_po[pbase + (long)rl*64 + 8*nf + 2*tig]     = o[nf][2*h2];
                g_po[pbase + (long)rl*64 + 8*nf + 2*tig + 1] = o[nf][2*h2 + 1];
            }
        }
    } else {
        #pragma unroll
        for (int h2 = 0; h2 < 2; h2++) {
            float inv = 1.0f / lrow[h2];
            int rl = w*16 + grp + 8*h2;
            long rowbase = ((long)(b*N_ + i0 + rl))*(H_*D_) + h*D_;
            #pragma unroll
            for (int nf = 0; nf < 8; nf++) {
                float f0 = o[nf][2*h2]     * inv;
                float f1 = o[nf][2*h2 + 1] * inv;
                uint32_t hi, lo; split2(f0, f1, hi, lo);
                long idx = rowbase + 8*nf + 2*tig;
                *(uint32_t*)&g_ah[idx] = hi;
                *(uint32_t*)&g_al[idx] = lo;
            }
        }
    }
}

// ---------------- split-KV merge for qt=0 ----------------
__global__ void attn_reduce()
{
    __shared__ float sm[NSP][64], sl[NSP][64], smx[64], slx[64];
    const int bh = blockIdx.x;
    const int tid = threadIdx.x;   // 256
    const int b = bh >> 3, h = bh & 7;

    {
        int s = tid >> 6, r = tid & 63;
        sm[s][r] = g_pm[((long)bh*NSP + s)*64 + r];
        sl[s][r] = g_pl[((long)bh*NSP + s)*64 + r];
    }
    __syncthreads();
    if (tid < 64) {
        float m = -1e30f;
        #pragma unroll
        for (int s = 0; s < NSP; s++) m = fmaxf(m, sm[s][tid]);
        float l = 0.f;
        #pragma unroll
        for (int s = 0; s < NSP; s++) {
            float ms = sm[s][tid];
            if (ms > -1e29f) l += __expf(ms - m) * sl[s][tid];
        }
        smx[tid] = m;
        slx[tid] = l;
    }
    __syncthreads();

    // 64 rows x 32 col-pairs; 256 threads x 8 iters
    for (int i = tid; i < 64*32; i += 256) {
        int r = i >> 5, cp = (i & 31)*2;
        float a0 = 0.f, a1 = 0.f;
        #pragma unroll
        for (int s = 0; s < NSP; s++) {
            float ms = sm[s][r];
            if (ms > -1e29f) {
                float cf = __expf(ms - smx[r]);
                const float* po = &g_po[(((long)bh*NSP + s)*64 + r)*64 + cp];
                a0 += cf * po[0];
                a1 += cf * po[1];
            }
        }
        float inv = 1.0f / slx[r];
        uint32_t hi, lo; split2(a0*inv, a1*inv, hi, lo);
        long idx = ((long)(b*N_ + r))*(H_*D_) + h*D_ + cp;
        *(uint32_t*)&g_ah[idx] = hi;
        *(uint32_t*)&g_al[idx] = lo;
    }
}

// ---------------- launcher ----------------
extern "C" void kernel_launch(void* const* d_in, const int* in_sizes, int n_in,
                              void* d_out, int out_size)
{
    const float* x    = (const float*)d_in[0];
    const float* Wq   = (const float*)d_in[1];
    const float* Wk   = (const float*)d_in[2];
    const float* Wv   = (const float*)d_in[3];
    const float* Wrel = (const float*)d_in[4];
    const float* cb   = (const float*)d_in[5];
    const float* pb   = (const float*)d_in[6];
    const float* Wo   = (const float*)d_in[7];
    const float* bo   = (const float*)d_in[8];
    const float* pos  = (const float*)d_in[9];
    const unsigned char* lmu = (const unsigned char*)d_in[10];
    const unsigned char* isg = (const unsigned char*)d_in[11];
    float* out = (float*)d_out;

    cudaFuncSetAttribute(wmma_gemm, cudaFuncAttributeMaxDynamicSharedMemorySize, WG_SMEM);
    cudaFuncSetAttribute(attn_mma, cudaFuncAttributeMaxDynamicSharedMemorySize, ATTN2_SMEM);

    __nv_bfloat16 *xh_p, *xl_p, *wh_p, *wl_p, *woh_p, *wol_p, *ah_p, *al_p;
    cudaGetSymbolAddress((void**)&xh_p,  g_xh);
    cudaGetSymbolAddress((void**)&xl_p,  g_xl);
    cudaGetSymbolAddress((void**)&wh_p,  g_wh);
    cudaGetSymbolAddress((void**)&wl_p,  g_wl);
    cudaGetSymbolAddress((void**)&woh_p, g_woh);
    cudaGetSymbolAddress((void**)&wol_p, g_wol);
    cudaGetSymbolAddress((void**)&ah_p,  g_ah);
    cudaGetSymbolAddress((void**)&al_p,  g_al);

    pre_kernel<<<NXB + NPB + NTB + NAB, 256>>>(x, pos, Wq, Wk, Wv, Wo, Wrel,
                                               lmu, isg);                    // 1
    wmma_gemm<<<384, 256, WG_SMEM>>>(xh_p, xl_p, wh_p, wl_p,
                                     cb, pb, nullptr, DIM_, 0);              // 2
    attn_mma<<<dim3(24 + NSP - 1, B_*H_), 128, ATTN2_SMEM>>>();              // 3
    attn_reduce<<<B_*H_, 256>>>();                                           // 4
    wmma_gemm<<<dim3(24, 12), 256, WG_SMEM>>>(ah_p, al_p, woh_p, wol_p,
                                              bo, nullptr, out, 512, 1);     // 5
}

// round 15
// speedup vs baseline: 1.2325x; 1.0133x over previous
#include <cuda_runtime.h>
#include <cuda_bf16.h>
#include <math.h>
#include <stdint.h>

#define B_   2
#define N_   1536
#define DIM_ 1536
#define H_   8
#define D_   64
#define P_   3071      // 2N-1
#define RP_  3072      // padded row stride for rel tables
#define QT_  24        // N/64 tiles
#define NSP  4         // splits for qt=0

// ---------------- device scratch (zero-initialized statics) ----------------
__device__ unsigned char g_tact[B_*QT_*QT_];
__device__ unsigned long long g_mbits[B_*QT_*QT_*64];

__device__ float g_po[16*NSP*64*64];   // qt=0 partial o (unnormalized)
__device__ float g_pm[16*NSP*64];      // partial row max
__device__ float g_pl[16*NSP*64];      // partial row sum

__device__ __nv_bfloat16 g_xh[B_*N_*DIM_];
__device__ __nv_bfloat16 g_xl[B_*N_*DIM_];
__device__ __nv_bfloat16 g_ph[RP_*192];
__device__ __nv_bfloat16 g_pl2[RP_*192];
__device__ __nv_bfloat16 g_wh[1536*DIM_];
__device__ __nv_bfloat16 g_wl[1536*DIM_];
__device__ __nv_bfloat16 g_wrh[512*192];
__device__ __nv_bfloat16 g_wrl[512*192];
__device__ __nv_bfloat16 g_woh[1536*512];
__device__ __nv_bfloat16 g_wol[1536*512];
__device__ __nv_bfloat16 g_ah[B_*N_*H_*D_];
__device__ __nv_bfloat16 g_al[B_*N_*H_*D_];
__device__ __nv_bfloat16 g_qh[B_*H_*N_*D_];
__device__ __nv_bfloat16 g_ql[B_*H_*N_*D_];
__device__ __nv_bfloat16 g_qph[B_*H_*N_*D_];
__device__ __nv_bfloat16 g_qpl[B_*H_*N_*D_];
__device__ __nv_bfloat16 g_kh[B_*H_*N_*D_];
__device__ __nv_bfloat16 g_kl[B_*H_*N_*D_];
__device__ __nv_bfloat16 g_vth[B_*H_*D_*N_];
__device__ __nv_bfloat16 g_vtl[B_*H_*D_*N_];
__device__ __nv_bfloat16 g_rh[H_*RP_*D_];
__device__ __nv_bfloat16 g_rl[H_*RP_*D_];

// ---------------- helpers ----------------
__device__ __forceinline__ uint32_t smem_to_u32(const void* p) {
    uint32_t a;
    asm("{ .reg .u64 t; cvta.to.shared.u64 t, %1; cvt.u32.u64 %0, t; }" : "=r"(a) : "l"(p));
    return a;
}
__device__ __forceinline__ void cp_async16(uint32_t saddr, const void* g) {
    asm volatile("cp.async.cg.shared.global [%0], [%1], 16;" :: "r"(saddr), "l"(g));
}
#define CP_COMMIT() asm volatile("cp.async.commit_group;" ::: "memory")
#define CP_WAIT0()  asm volatile("cp.async.wait_group 0;" ::: "memory")
#define CP_WAIT1()  asm volatile("cp.async.wait_group 1;" ::: "memory")

__device__ __forceinline__ void mma_bf16(float* c, const uint32_t* a, const uint32_t* b) {
    asm volatile("mma.sync.aligned.m16n8k16.row.col.f32.bf16.bf16.f32 "
        "{%0,%1,%2,%3}, {%4,%5,%6,%7}, {%8,%9}, {%0,%1,%2,%3};"
        : "+f"(c[0]), "+f"(c[1]), "+f"(c[2]), "+f"(c[3])
        : "r"(a[0]), "r"(a[1]), "r"(a[2]), "r"(a[3]), "r"(b[0]), "r"(b[1]));
}
__device__ __forceinline__ void ldsm_x4(uint32_t* r, uint32_t addr) {
    asm volatile("ldmatrix.sync.aligned.m8n8.x4.shared.b16 {%0,%1,%2,%3}, [%4];"
        : "=r"(r[0]), "=r"(r[1]), "=r"(r[2]), "=r"(r[3]) : "r"(addr));
}
__device__ __forceinline__ void split2(float f0, float f1, uint32_t& hi, uint32_t& lo) {
    __nv_bfloat16 h0 = __float2bfloat16(f0), h1 = __float2bfloat16(f1);
    __nv_bfloat162 hh(h0, h1);
    hi = *(uint32_t*)&hh;
    __nv_bfloat16 l0 = __float2bfloat16(f0 - __bfloat162float(h0));
    __nv_bfloat16 l1 = __float2bfloat16(f1 - __bfloat162float(h1));
    __nv_bfloat162 ll(l0, l1);
    lo = *(uint32_t*)&ll;
}
__device__ __forceinline__ bool rd_mask(const unsigned char* p, long idx, int mt) {
    if (mt == 0) return p[idx] != 0;
    if (mt == 1) return ((const int*)p)[idx] != 0;
    return ((const float*)p)[idx] != 0.0f;
}
__device__ __forceinline__ uint32_t swz(uint32_t base, int r, int c) {
    return base + (uint32_t)r*64u + (uint32_t)((c ^ ((r >> 1) & 3)) << 4);
}

// ---------------- fused pre-processing kernel ----------------
#define NXB 4608
#define NPB 576
#define NTB 3840
#define NAB 288

__global__ void pre_kernel(const float* __restrict__ x, const float* __restrict__ pos,
                           const float* __restrict__ Wq, const float* __restrict__ Wk,
                           const float* __restrict__ Wv, const float* __restrict__ Wo,
                           const float* __restrict__ Wrel,
                           const unsigned char* __restrict__ lm,
                           const unsigned char* __restrict__ isg)
{
    __shared__ float t[32][33];
    __shared__ unsigned int cg[8];
    __shared__ unsigned char anyA[8];
    const int id = blockIdx.x;
    const int tid = threadIdx.x;

    if (id < NXB + NPB) {
        const float* s; __nv_bfloat16 *h, *l; int n4, base;
        if (id < NXB) { s = x; h = g_xh; l = g_xl; n4 = B_*N_*DIM_/4; base = id; }
        else          { s = pos; h = g_ph; l = g_pl2; n4 = P_*192/4; base = id - NXB; }
        int i = base*256 + tid;
        if (i >= n4) return;
        float4 v = ((const float4*)s)[i];
        float a[4] = {v.x, v.y, v.z, v.w};
        __nv_bfloat16 hh[4], ll[4];
        #pragma unroll
        for (int j = 0; j < 4; j++) {
            hh[j] = __float2bfloat16(a[j]);
            ll[j] = __float2bfloat16(a[j] - __bfloat162float(hh[j]));
        }
        ((__nv_bfloat162*)h)[i*2+0] = __nv_bfloat162(hh[0], hh[1]);
        ((__nv_bfloat162*)h)[i*2+1] = __nv_bfloat162(hh[2], hh[3]);
        ((__nv_bfloat162*)l)[i*2+0] = __nv_bfloat162(ll[0], ll[1]);
        ((__nv_bfloat162*)l)[i*2+1] = __nv_bfloat162(ll[2], ll[3]);
    } else if (id < NXB + NPB + NTB) {
        int idx2 = id - NXB - NPB;
        int job = idx2 / 768, idx = idx2 % 768;
        const float* src; __nv_bfloat16 *dh, *dl;
        int R, C, c0, r0;
        if (job < 3) {
            src = (job == 0) ? Wq : (job == 1) ? Wk : Wv;
            dh = g_wh + (long)job*512*1536; dl = g_wl + (long)job*512*1536;
            R = 1536; C = 512;
            c0 = (idx & 15)*32; r0 = (idx >> 4)*32;
        } else if (job == 3) {
            src = Wo; dh = g_woh; dl = g_wol;
            R = 512; C = 1536;
            c0 = (idx % 48)*32; r0 = (idx / 48)*32;
        } else {
            if (idx >= 96) return;
            src = Wrel; dh = g_wrh; dl = g_wrl;
            R = 192; C = 512;
            c0 = (idx & 15)*32; r0 = (idx >> 4)*32;
        }
        int tx = tid & 31, ty = tid >> 5;
        #pragma unroll
        for (int i = 0; i < 4; i++)
            t[ty + i*8][tx] = src[(long)(r0 + ty + i*8)*C + c0 + tx];
        __syncthreads();
        #pragma unroll
        for (int i = 0; i < 4; i++) {
            int c = c0 + ty + i*8, r = r0 + tx;
            float v = t[tx][ty + i*8];
            __nv_bfloat16 hv = __float2bfloat16(v);
            dh[(long)c*R + r] = hv;
            dl[(long)c*R + r] = __float2bfloat16(v - __bfloat162float(hv));
        }
    } else {
        int tb = id - NXB - NPB - NTB;
        int g  = tid >> 6;
        int r  = tid & 63;
        int w  = tid >> 5;
        int lane = tid & 31;
        int tt = tb*4 + g;
        int jt = tt % QT_;
        int qt = (tt / QT_) % QT_;
        int b  = tt / (QT_*QT_);
        int i0 = qt*64, j0 = jt*64;
        unsigned int w0 = *(const unsigned int*)lm;
        int mt;
        if ((w0 & 0xFFu) == 1u && ((w0 >> 8) & 0xFFu) == 1u) mt = 0;
        else if (w0 == 1u) mt = 1;
        else mt = 2;

        bool cpred = rd_mask(isg, (long)b*N_ + j0 + r, mt);
        unsigned int cw = __ballot_sync(0xffffffffu, cpred);
        if (lane == 0) cg[w] = cw;

        bool rg = rd_mask(isg, (long)b*N_ + i0 + r, mt);

        unsigned long long rowbits = 0ull;
        if (mt == 0) {
            const uint4* rp = (const uint4*)(lm + (long)(i0 + r)*N_ + j0);
            #pragma unroll
            for (int q = 0; q < 4; q++) {
                uint4 v = rp[q];
                unsigned int ws[4] = {v.x, v.y, v.z, v.w};
                #pragma unroll
                for (int k = 0; k < 4; k++) {
                    unsigned int nz  = __vcmpne4(ws[k], 0u) & 0x01010101u;
                    unsigned int nib = (nz * 0x01020408u) >> 24;
                    rowbits |= (unsigned long long)(nib & 0xFu) << (q*16 + k*4);
                }
            }
        } else {
            for (int c = 0; c < 64; c++)
                rowbits |= (unsigned long long)(rd_mask(lm, (long)(i0+r)*N_ + j0 + c, mt) ? 1 : 0) << c;
        }
        __syncthreads();
        unsigned long long colbits = (unsigned long long)cg[g*2]
                                   | ((unsigned long long)cg[g*2+1] << 32);
        unsigned long long bits = rg ? ~0ull : (rowbits | colbits);
        g_mbits[(long)tt*64 + r] = bits;
        unsigned int anyw = __ballot_sync(0xffffffffu, bits != 0ull);
        if (lane == 0) anyA[w] = anyw ? 1 : 0;
        __syncthreads();
        if (r == 0) g_tact[tt] = (unsigned char)(anyA[g*2] | anyA[g*2+1]);
    }
}

// ---------------- warp-MMA bf16 split-precision GEMM (3-stage, swizzled) ----------------
#define TBYTES 8192
#define STAGE  (4*TBYTES)
#define NSTG   3
#define WG_SMEM (NSTG*STAGE)

__global__ __launch_bounds__(256, 2)
void wmma_gemm(const __nv_bfloat16* __restrict__ Ah, const __nv_bfloat16* __restrict__ Al,
               const __nv_bfloat16* __restrict__ Bh, const __nv_bfloat16* __restrict__ Bl,
               const float* __restrict__ bias, const float* __restrict__ bias2,
               float* __restrict__ Cout, int K, int mode)
{
    extern __shared__ char smem[];
    const uint32_t sb = smem_to_u32(smem);
    const int tid = threadIdx.x;
    const int lane = tid & 31;
    const int wid = tid >> 5;
    const int warp_m = wid >> 2;
    const int warp_n = wid & 3;
    const int grp = lane >> 2;
    const int tig = lane & 3;

    int m0, n0, Keff = K, mode_eff = mode;
    const char* srcs[4];
    if (mode == 0) {
        int id = blockIdx.x;
        if (id < 288) {
            m0 = (id % 24) * 128; n0 = (id / 24) * 128;
            srcs[0] = (const char*)Ah; srcs[1] = (const char*)Al;
            srcs[2] = (const char*)Bh; srcs[3] = (const char*)Bl;
        } else {
            id -= 288;
            m0 = (id % 24) * 128; n0 = (id / 24) * 128;
            srcs[0] = (const char*)g_ph;  srcs[1] = (const char*)g_pl2;
            srcs[2] = (const char*)g_wrh; srcs[3] = (const char*)g_wrl;
            Keff = 192; mode_eff = 2;
        }
    } else {
        m0 = blockIdx.x * 128; n0 = blockIdx.y * 128;
        srcs[0] = (const char*)Ah; srcs[1] = (const char*)Al;
        srcs[2] = (const char*)Bh; srcs[3] = (const char*)Bl;
    }

    const int arow_l = lane & 15;
    const int achk_l = lane >> 4;
    const int brow_l = ((lane >> 4) << 3) + (lane & 7);
    const int bchk_l = (lane >> 3) & 1;

    const int rb[4] = {m0, m0, n0, n0};
    const long rowB = (long)Keff * 2;

    auto issue_stage = [&](int kt, int st) {
        const uint32_t sbase = sb + st*STAGE;
        #pragma unroll
        for (int l = 0; l < 8; l++) {
            int i = tid + l*256;
            int t = i >> 9, r = (i >> 2) & 127, c = i & 3;
            const char* g = srcs[t] + (long)(rb[t] + r)*rowB + kt*64 + c*16;
            cp_async16(swz(sbase + t*TBYTES, r, c), g);
        }
        CP_COMMIT();
    };

    float acc[4][4][4];
    #pragma unroll
    for (int i = 0; i < 4; i++)
        #pragma unroll
        for (int j = 0; j < 4; j++)
            #pragma unroll
            for (int e = 0; e < 4; e++) acc[i][j][e] = 0.f;

    const int nk = Keff / 32;
    issue_stage(0, 0);
    issue_stage(1, 1);

    for (int kt = 0; kt < nk; kt++) {
        CP_WAIT1();
        __syncthreads();
        if (kt + 2 < nk) issue_stage(kt + 2, (kt + 2) % NSTG);

        const uint32_t stg = sb + (kt % NSTG)*STAGE;
        const uint32_t aoffh = stg + 0*TBYTES;
        const uint32_t aoffl = stg + 1*TBYTES;
        const uint32_t boffh = stg + 2*TBYTES;
        const uint32_t boffl = stg + 3*TBYTES;

        #pragma unroll
        for (int ks = 0; ks < 2; ks++) {
            uint32_t bh[4][2], bl[4][2];
            #pragma unroll
            for (int jp = 0; jp < 2; jp++) {
                int brw = warp_n*32 + jp*16 + brow_l;
                int bck = ks*2 + bchk_l;
                uint32_t r4[4];
                ldsm_x4(r4, swz(boffh, brw, bck));
                bh[2*jp][0] = r4[0]; bh[2*jp][1] = r4[1];
                bh[2*jp+1][0] = r4[2]; bh[2*jp+1][1] = r4[3];
                ldsm_x4(r4, swz(boffl, brw, bck));
                bl[2*jp][0] = r4[0]; bl[2*jp][1] = r4[1];
                bl[2*jp+1][0] = r4[2]; bl[2*jp+1][1] = r4[3];
            }
            #pragma unroll
            for (int i = 0; i < 4; i++) {
                int arw = warp_m*64 + i*16 + arow_l;
                int ack = ks*2 + achk_l;
                uint32_t ah[4], al[4];
                ldsm_x4(ah, swz(aoffh, arw, ack));
                ldsm_x4(al, swz(aoffl, arw, ack));
                #pragma unroll
                for (int j = 0; j < 4; j++) mma_bf16(acc[i][j], ah, bh[j]);
                #pragma unroll
                for (int j = 0; j < 4; j++) mma_bf16(acc[i][j], ah, bl[j]);
                #pragma unroll
                for (int j = 0; j < 4; j++) mma_bf16(acc[i][j], al, bh[j]);
            }
        }
    }

    // epilogue
    #pragma unroll
    for (int i = 0; i < 4; i++) {
        #pragma unroll
        for (int j = 0; j < 4; j++) {
            const int r0 = m0 + warp_m*64 + i*16 + grp;
            const int c0 = n0 + warp_n*32 + j*8 + 2*tig;
            #pragma unroll
            for (int half = 0; half < 2; half++) {
                const int row = r0 + half*8;
                float v0 = acc[i][j][half*2 + 0];
                float v1 = acc[i][j][half*2 + 1];
                if (mode_eff == 1) {
                    Cout[(long)row*1536 + c0]     = v0 + bias[c0];
                    Cout[(long)row*1536 + c0 + 1] = v1 + bias[c0 + 1];
                } else if (mode_eff == 2) {
                    const int h = c0 >> 6, d = c0 & 63;
                    uint32_t hi, lo; split2(v0, v1, hi, lo);
                    long idx = ((long)h*RP_ + row)*D_ + d;
                    *(uint32_t*)&g_rh[idx] = hi;
                    *(uint32_t*)&g_rl[idx] = lo;
                } else {
                    const int sel = c0 >> 9, pc = c0 & 511;
                    const int h = pc >> 6, d = pc & 63;
                    const int bb = (row >= N_) ? 1 : 0;
                    const int ii = row - bb*N_;
                    const int bhd = bb*H_ + h;
                    if (sel == 0) {
                        float s0 = v0*0.125f, s1 = v1*0.125f;
                        long idx = ((long)bhd*N_ + ii)*D_ + d;
                        uint32_t hi, lo;
                        split2(s0 + bias[pc], s1 + bias[pc + 1], hi, lo);
                        *(uint32_t*)&g_qh[idx] = hi;
                        *(uint32_t*)&g_ql[idx] = lo;
                        split2(s0 + bias2[pc], s1 + bias2[pc + 1], hi, lo);
                        *(uint32_t*)&g_qph[idx] = hi;
                        *(uint32_t*)&g_qpl[idx] = lo;
                    } else if (sel == 1) {
                        uint32_t hi, lo; split2(v0, v1, hi, lo);
                        long idx = ((long)bhd*N_ + ii)*D_ + d;
                        *(uint32_t*)&g_kh[idx] = hi;
                        *(uint32_t*)&g_kl[idx] = lo;
                    } else {
                        __nv_bfloat16 h0 = __float2bfloat16(v0);
                        __nv_bfloat16 h1 = __float2bfloat16(v1);
                        long i0x = ((long)bhd*D_ + d)*N_ + ii;
                        long i1x = ((long)bhd*D_ + d + 1)*N_ + ii;
                        g_vth[i0x] = h0;
                        g_vth[i1x] = h1;
                        g_vtl[i0x] = __float2bfloat16(v0 - __bfloat162float(h0));
                        g_vtl[i1x] = __float2bfloat16(v1 - __bfloat162float(h1));
                    }
                }
            }
        }
    }
}

// ---------------- mma.sync flash attention (banded G + split-KV for qt=0) ----------------
#define AK_H   0u
#define AK_L   9216u
#define AVT_H  18432u
#define AVT_L  27648u
#define AR_H   36864u
#define AR_L   55296u
#define AG     73728u
#define ATTN2_SMEM (73728 + 64*132*4)

__global__ __launch_bounds__(128, 2)
void attn_mma()
{
    extern __shared__ char sm2[];
    const uint32_t sb = smem_to_u32(sm2);
    float* sG = (float*)(sm2 + AG);

    const int tid = threadIdx.x;
    const int lane = tid & 31;
    const int w = tid >> 5;
    const int grp = lane >> 2;
    const int tig = lane & 3;
    const int qs = blockIdx.x;          // 0..26
    const int bh = blockIdx.y;
    const int b = bh >> 3, h = bh & 7;

    int qt, sp, jt_lo, jt_hi;
    if (qs < 24) { qt = qs; sp = 0; } else { qt = 0; sp = qs - 23; }
    if (qt == 0) { jt_lo = sp*6; jt_hi = jt_lo + 6; }
    else         { jt_lo = 0; jt_hi = QT_; }
    const int i0 = qt * 64;

    const int brow_l = ((lane >> 4) << 3) + (lane & 7);
    const int bcol_l = ((lane >> 3) & 1) * 16;
    const int gb_lo = 3 - w;
    const int gb_hi = 7 - w;

    const __nv_bfloat16* qbh = g_qh  + (long)bh*N_*D_;
    const __nv_bfloat16* qbl = g_ql  + (long)bh*N_*D_;
    const __nv_bfloat16* pqh = g_qph + (long)bh*N_*D_;
    const __nv_bfloat16* pql = g_qpl + (long)bh*N_*D_;
    const int rq0 = i0 + w*16 + grp, rq1 = rq0 + 8;
    uint32_t qfh[4][4], qfl[4][4], qgh[4][4], qgl[4][4];
    #pragma unroll
    for (int kf = 0; kf < 4; kf++) {
        qfh[kf][0] = *(const uint32_t*)(qbh + (long)rq0*D_ + kf*16 + 2*tig);
        qfh[kf][1] = *(const uint32_t*)(qbh + (long)rq1*D_ + kf*16 + 2*tig);
        qfh[kf][2] = *(const uint32_t*)(qbh + (long)rq0*D_ + kf*16 + 8 + 2*tig);
        qfh[kf][3] = *(const uint32_t*)(qbh + (long)rq1*D_ + kf*16 + 8 + 2*tig);
        qfl[kf][0] = *(const uint32_t*)(qbl + (long)rq0*D_ + kf*16 + 2*tig);
        qfl[kf][1] = *(const uint32_t*)(qbl + (long)rq1*D_ + kf*16 + 2*tig);
        qfl[kf][2] = *(const uint32_t*)(qbl + (long)rq0*D_ + kf*16 + 8 + 2*tig);
        qfl[kf][3] = *(const uint32_t*)(qbl + (long)rq1*D_ + kf*16 + 8 + 2*tig);
        qgh[kf][0] = *(const uint32_t*)(pqh + (long)rq0*D_ + kf*16 + 2*tig);
        qgh[kf][1] = *(const uint32_t*)(pqh + (long)rq1*D_ + kf*16 + 2*tig);
        qgh[kf][2] = *(const uint32_t*)(pqh + (long)rq0*D_ + kf*16 + 8 + 2*tig);
        qgh[kf][3] = *(const uint32_t*)(pqh + (long)rq1*D_ + kf*16 + 8 + 2*tig);
        qgl[kf][0] = *(const uint32_t*)(pql + (long)rq0*D_ + kf*16 + 2*tig);
        qgl[kf][1] = *(const uint32_t*)(pql + (long)rq1*D_ + kf*16 + 2*tig);
        qgl[kf][2] = *(const uint32_t*)(pql + (long)rq0*D_ + kf*16 + 8 + 2*tig);
        qgl[kf][3] = *(const uint32_t*)(pql + (long)rq1*D_ + kf*16 + 8 + 2*tig);
    }

    float o[8][4];
    #pragma unroll
    for (int nf = 0; nf < 8; nf++)
        #pragma unroll
        for (int e = 0; e < 4; e++) o[nf][e] = 0.f;
    float mrow[2] = {-1e30f, -1e30f};
    float lrow[2] = {0.f, 0.f};

    const unsigned char* tact = &g_tact[(b*QT_ + qt)*QT_];
    const long kbase  = (long)bh*N_*D_;
    const long vbase  = (long)bh*D_*N_;
    const long rbase  = (long)h*RP_*D_;

    for (int jt = jt_lo; jt < jt_hi; jt++) {
        if (!tact[jt]) continue;
        const int j0 = jt*64;
        const int p0 = j0 - i0 + (N_ - 1) - 63;

        __syncthreads();
        #pragma unroll
        for (int l = 0; l < 4; l++) {
            int i = tid + l*128;
            int r = i >> 3, c = i & 7;
            long krow = (kbase + (long)(j0 + r)*D_)*2;
            long vrow = (vbase + (long)r*N_ + j0)*2;
            cp_async16(sb + AK_H  + r*144 + c*16, (const char*)g_kh  + krow + c*16);
            cp_async16(sb + AK_L  + r*144 + c*16, (const char*)g_kl  + krow + c*16);
            cp_async16(sb + AVT_H + r*144 + c*16, (const char*)g_vth + vrow + c*16);
            cp_async16(sb + AVT_L + r*144 + c*16, (const char*)g_vtl + vrow + c*16);
        }
        #pragma unroll
        for (int l = 0; l < 8; l++) {
            int i = tid + l*128;
            int r = i >> 3, c = i & 7;
            long rrow = (rbase + (long)(p0 + r)*D_)*2;
            cp_async16(sb + AR_H + r*144 + c*16, (const char*)g_rh + rrow + c*16);
            cp_async16(sb + AR_L + r*144 + c*16, (const char*)g_rl + rrow + c*16);
        }
        CP_COMMIT();

        const unsigned long long* mb = g_mbits + ((long)(b*QT_ + qt)*QT_ + jt)*64;
        unsigned long long mw0 = mb[w*16 + grp];
        unsigned long long mw1 = mb[w*16 + grp + 8];

        CP_WAIT0();
        __syncthreads();

        float ca[8][4];
        #pragma unroll
        for (int nf = 0; nf < 8; nf++)
            #pragma unroll
            for (int e = 0; e < 4; e++) ca[nf][e] = 0.f;
        #pragma unroll
        for (int kf = 0; kf < 4; kf++) {
            #pragma unroll
            for (int np = 0; np < 4; np++) {
                uint32_t ro = (uint32_t)(np*16 + brow_l)*144 + kf*32 + bcol_l;
                uint32_t kh4[4], kl4[4];
                ldsm_x4(kh4, sb + AK_H + ro);
                ldsm_x4(kl4, sb + AK_L + ro);
                mma_bf16(ca[2*np],   qfh[kf], &kh4[0]);
                mma_bf16(ca[2*np+1], qfh[kf], &kh4[2]);
                mma_bf16(ca[2*np],   qfh[kf], &kl4[0]);
                mma_bf16(ca[2*np+1], qfh[kf], &kl4[2]);
                mma_bf16(ca[2*np],   qfl[kf], &kh4[0]);
                mma_bf16(ca[2*np+1], qfl[kf], &kh4[2]);
            }
        }

        const int grow = w*16 + grp;
        #pragma unroll
        for (int gh = 0; gh < 2; gh++) {
            #pragma unroll
            for (int np = 0; np < 4; np++) {
                const int gb = gh*4 + np;
                if (gb < gb_lo || gb > gb_hi) continue;
                float ga0[4] = {0.f, 0.f, 0.f, 0.f};
                float ga1[4] = {0.f, 0.f, 0.f, 0.f};
                #pragma unroll
                for (int kf = 0; kf < 4; kf++) {
                    uint32_t ro = (uint32_t)(gb*16 + brow_l)*144 + kf*32 + bcol_l;
                    uint32_t rh4[4], rl4[4];
                    ldsm_x4(rh4, sb + AR_H + ro);
                    ldsm_x4(rl4, sb + AR_L + ro);
                    mma_bf16(ga0, qgh[kf], &rh4[0]);
                    mma_bf16(ga1, qgh[kf], &rh4[2]);
                    mma_bf16(ga0, qgh[kf], &rl4[0]);
                    mma_bf16(ga1, qgh[kf], &rl4[2]);
                    mma_bf16(ga0, qgl[kf], &rh4[0]);
                    mma_bf16(ga1, qgl[kf], &rh4[2]);
                }
                int col = gb*16 + 2*tig;
                sG[grow*132 + col]            = ga0[0];
                sG[grow*132 + col + 1]        = ga0[1];
                sG[(grow + 8)*132 + col]      = ga0[2];
                sG[(grow + 8)*132 + col + 1]  = ga0[3];
                sG[grow*132 + col + 8]        = ga1[0];
                sG[grow*132 + col + 9]        = ga1[1];
                sG[(grow + 8)*132 + col + 8]  = ga1[2];
                sG[(grow + 8)*132 + col + 9]  = ga1[3];
            }
        }
        __syncwarp();

        float pv0[16], pv1[16];
        #pragma unroll
        for (int h2 = 0; h2 < 2; h2++) {
            const int rl = grow + 8*h2;
            const unsigned long long mw = h2 ? mw1 : mw0;
            float* pvv = h2 ? pv1 : pv0;
            float lg[16];
            float tmax = -1e30f;
            #pragma unroll
            for (int nf = 0; nf < 8; nf++) {
                #pragma unroll
                for (int e = 0; e < 2; e++) {
                    int c = 8*nf + 2*tig + e;
                    int pp = c - rl + 63;
                    float val = ca[nf][2*h2 + e] + sG[rl*132 + pp];
                    bool act = (mw >> c) & 1ull;
                    float lv = act ? val : -1e30f;
                    lg[nf*2 + e] = lv;
                    tmax = fmaxf(tmax, lv);
                }
            }
            tmax = fmaxf(tmax, __shfl_xor_sync(0xffffffffu, tmax, 1));
            tmax = fmaxf(tmax, __shfl_xor_sync(0xffffffffu, tmax, 2));
            float nm = fmaxf(mrow[h2], tmax);
            float corr = __expf(mrow[h2] - nm);
            mrow[h2] = nm;
            float ps = 0.f;
            #pragma unroll
            for (int e2 = 0; e2 < 16; e2++) {
                float p = (lg[e2] <= -1e29f) ? 0.f : __expf(lg[e2] - nm);
                pvv[e2] = p;
                ps += p;
            }
            ps += __shfl_xor_sync(0xffffffffu, ps, 1);
            ps += __shfl_xor_sync(0xffffffffu, ps, 2);
            lrow[h2] = lrow[h2]*corr + ps;
            #pragma unroll
            for (int nf = 0; nf < 8; nf++) {
                o[nf][2*h2]     *= corr;
                o[nf][2*h2 + 1] *= corr;
            }
        }

        uint32_t pfh[4][4], pfl[4][4];
        #pragma unroll
        for (int kf = 0; kf < 4; kf++) {
            split2(pv0[(2*kf)*2],   pv0[(2*kf)*2+1],   pfh[kf][0], pfl[kf][0]);
            split2(pv1[(2*kf)*2],   pv1[(2*kf)*2+1],   pfh[kf][1], pfl[kf][1]);
            split2(pv0[(2*kf+1)*2], pv0[(2*kf+1)*2+1], pfh[kf][2], pfl[kf][2]);
            split2(pv1[(2*kf+1)*2], pv1[(2*kf+1)*2+1], pfh[kf][3], pfl[kf][3]);
        }

        #pragma unroll
        for (int kf = 0; kf < 4; kf++) {
            #pragma unroll
            for (int np = 0; np < 4; np++) {
                uint32_t ro = (uint32_t)(np*16 + brow_l)*144 + kf*32 + bcol_l;
                uint32_t vh4[4], vl4[4];
                ldsm_x4(vh4, sb + AVT_H + ro);
                ldsm_x4(vl4, sb + AVT_L + ro);
                mma_bf16(o[2*np],   pfh[kf], &vh4[0]);
                mma_bf16(o[2*np+1], pfh[kf], &vh4[2]);
                mma_bf16(o[2*np],   pfh[kf], &vl4[0]);
                mma_bf16(o[2*np+1], pfh[kf], &vl4[2]);
                mma_bf16(o[2*np],   pfl[kf], &vh4[0]);
                mma_bf16(o[2*np+1], pfl[kf], &vh4[2]);
            }
        }
    }

    // ---- epilogue ----
    if (qt == 0) {
        const long pbase = ((long)bh*NSP + sp)*64*64;
        #pragma unroll
        for (int h2 = 0; h2 < 2; h2++) {
            int rl = w*16 + grp + 8*h2;
            if (tig == 0) {
                g_pm[((long)bh*NSP + sp)*64 + rl] = mrow[h2];
                g_pl[((long)bh*NSP + sp)*64 + rl] = lrow[h2];
            }
            #pragma unroll
            for (int nf = 0; nf < 8; nf++) {
                g_po[pbase + (long)rl*64 + 8*nf + 2*tig]     = o[nf][2*h2];
                g_po[pbase + (long)rl*64 + 8*nf + 2*tig + 1] = o[nf][2*h2 + 1];
            }
        }
    } else {
        #pragma unroll
        for (int h2 = 0; h2 < 2; h2++) {
            float inv = 1.0f / lrow[h2];
            int rl = w*16 + grp + 8*h2;
            long rowbase = ((long)(b*N_ + i0 + rl))*(H_*D_) + h*D_;
            #pragma unroll
            for (int nf = 0; nf < 8; nf++) {
                float f0 = o[nf][2*h2]     * inv;
                float f1 = o[nf][2*h2 + 1] * inv;
                uint32_t hi, lo; split2(f0, f1, hi, lo);
                long idx = rowbase + 8*nf + 2*tig;
                *(uint32_t*)&g_ah[idx] = hi;
                *(uint32_t*)&g_al[idx] = lo;
            }
        }
    }
}

// ---------------- split-KV merge for qt=0 (wide grid) ----------------
// grid (16, 8): block = one (b,h) x 8-row group; 256 thr = 8 rows x 32 col-pairs
__global__ void attn_reduce()
{
    __shared__ float sm[NSP][8], sl[NSP][8], smx[8], slx[8];
    const int bh = blockIdx.x;
    const int rg = blockIdx.y;
    const int tid = threadIdx.x;
    const int b = bh >> 3, h = bh & 7;

    if (tid < NSP*8) {
        int s = tid >> 3, r = tid & 7;
        sm[s][r] = g_pm[((long)bh*NSP + s)*64 + rg*8 + r];
        sl[s][r] = g_pl[((long)bh*NSP + s)*64 + rg*8 + r];
    }
    __syncthreads();
    if (tid < 8) {
        float m = -1e30f;
        #pragma unroll
        for (int s = 0; s < NSP; s++) m = fmaxf(m, sm[s][tid]);
        float l = 0.f;
        #pragma unroll
        for (int s = 0; s < NSP; s++) {
            float ms = sm[s][tid];
            if (ms > -1e29f) l += __expf(ms - m) * sl[s][tid];
        }
        smx[tid] = m;
        slx[tid] = l;
    }
    __syncthreads();

    const int rl = tid >> 5;          // row within group
    const int r  = rg*8 + rl;         // row within 64
    const int cp = (tid & 31)*2;
    float a0 = 0.f, a1 = 0.f;
    #pragma unroll
    for (int s = 0; s < NSP; s++) {
        float ms = sm[s][rl];
        if (ms > -1e29f) {
            float cf = __expf(ms - smx[rl]);
            const float* po = &g_po[(((long)bh*NSP + s)*64 + r)*64 + cp];
            a0 += cf * po[0];
            a1 += cf * po[1];
        }
    }
    float inv = 1.0f / slx[rl];
    uint32_t hi, lo; split2(a0*inv, a1*inv, hi, lo);
    long idx = ((long)(b*N_ + r))*(H_*D_) + h*D_ + cp;
    *(uint32_t*)&g_ah[idx] = hi;
    *(uint32_t*)&g_al[idx] = lo;
}

// ---------------- launcher ----------------
extern "C" void kernel_launch(void* const* d_in, const int* in_sizes, int n_in,
                              void* d_out, int out_size)
{
    const float* x    = (const float*)d_in[0];
    const float* Wq   = (const float*)d_in[1];
    const float* Wk   = (const float*)d_in[2];
    const float* Wv   = (const float*)d_in[3];
    const float* Wrel = (const float*)d_in[4];
    const float* cb   = (const float*)d_in[5];
    const float* pb   = (const float*)d_in[6];
    const float* Wo   = (const float*)d_in[7];
    const float* bo   = (const float*)d_in[8];
    const float* pos  = (const float*)d_in[9];
    const unsigned char* lmu = (const unsigned char*)d_in[10];
    const unsigned char* isg = (const unsigned char*)d_in[11];
    float* out = (float*)d_out;

    cudaFuncSetAttribute(wmma_gemm, cudaFuncAttributeMaxDynamicSharedMemorySize, WG_SMEM);
    cudaFuncSetAttribute(attn_mma, cudaFuncAttributeMaxDynamicSharedMemorySize, ATTN2_SMEM);

    __nv_bfloat16 *xh_p, *xl_p, *wh_p, *wl_p, *woh_p, *wol_p, *ah_p, *al_p;
    cudaGetSymbolAddress((void**)&xh_p,  g_xh);
    cudaGetSymbolAddress((void**)&xl_p,  g_xl);
    cudaGetSymbolAddress((void**)&wh_p,  g_wh);
    cudaGetSymbolAddress((void**)&wl_p,  g_wl);
    cudaGetSymbolAddress((void**)&woh_p, g_woh);
    cudaGetSymbolAddress((void**)&wol_p, g_wol);
    cudaGetSymbolAddress((void**)&ah_p,  g_ah);
    cudaGetSymbolAddress((void**)&al_p,  g_al);

    pre_kernel<<<NXB + NPB + NTB + NAB, 256>>>(x, pos, Wq, Wk, Wv, Wo, Wrel,
                                               lmu, isg);                    // 1
    wmma_gemm<<<384, 256, WG_SMEM>>>(xh_p, xl_p, wh_p, wl_p,
                                     cb, pb, nullptr, DIM_, 0);              // 2
    attn_mma<<<dim3(24 + NSP - 1, B_*H_), 128, ATTN2_SMEM>>>();              // 3
    attn_reduce<<<dim3(B_*H_, 8), 256>>>();                                  // 4
    wmma_gemm<<<dim3(24, 12), 256, WG_SMEM>>>(ah_p, al_p, woh_p, wol_p,
                                              bo, nullptr, out, 512, 1);     // 5
}

// round 16
// speedup vs baseline: 1.2444x; 1.0096x over previous
#include <cuda_runtime.h>
#include <cuda_bf16.h>
#include <math.h>
#include <stdint.h>

#define B_   2
#define N_   1536
#define DIM_ 1536
#define H_   8
#define D_   64
#define P_   3071      // 2N-1
#define RP_  3072      // padded row stride for rel tables
#define QT_  24        // N/64 tiles
#define NSP  6         // splits for qt=0 (4 tiles each)

// ---------------- device scratch (zero-initialized statics) ----------------
__device__ unsigned char g_tact[B_*QT_*QT_];
__device__ unsigned long long g_mbits[B_*QT_*QT_*64];
__device__ unsigned int g_cnt[16];     // split-arrival counters (reset by pre_kernel)

__device__ float g_po[16*NSP*64*64];   // qt=0 partial o (unnormalized)
__device__ float g_pm[16*NSP*64];      // partial row max
__device__ float g_pl[16*NSP*64];      // partial row sum

__device__ __nv_bfloat16 g_xh[B_*N_*DIM_];
__device__ __nv_bfloat16 g_xl[B_*N_*DIM_];
__device__ __nv_bfloat16 g_ph[RP_*192];
__device__ __nv_bfloat16 g_pl2[RP_*192];
__device__ __nv_bfloat16 g_wh[1536*DIM_];
__device__ __nv_bfloat16 g_wl[1536*DIM_];
__device__ __nv_bfloat16 g_wrh[512*192];
__device__ __nv_bfloat16 g_wrl[512*192];
__device__ __nv_bfloat16 g_woh[1536*512];
__device__ __nv_bfloat16 g_wol[1536*512];
__device__ __nv_bfloat16 g_ah[B_*N_*H_*D_];
__device__ __nv_bfloat16 g_al[B_*N_*H_*D_];
__device__ __nv_bfloat16 g_qh[B_*H_*N_*D_];
__device__ __nv_bfloat16 g_ql[B_*H_*N_*D_];
__device__ __nv_bfloat16 g_qph[B_*H_*N_*D_];
__device__ __nv_bfloat16 g_qpl[B_*H_*N_*D_];
__device__ __nv_bfloat16 g_kh[B_*H_*N_*D_];
__device__ __nv_bfloat16 g_kl[B_*H_*N_*D_];
__device__ __nv_bfloat16 g_vth[B_*H_*D_*N_];
__device__ __nv_bfloat16 g_vtl[B_*H_*D_*N_];
__device__ __nv_bfloat16 g_rh[H_*RP_*D_];
__device__ __nv_bfloat16 g_rl[H_*RP_*D_];

// ---------------- helpers ----------------
__device__ __forceinline__ uint32_t smem_to_u32(const void* p) {
    uint32_t a;
    asm("{ .reg .u64 t; cvta.to.shared.u64 t, %1; cvt.u32.u64 %0, t; }" : "=r"(a) : "l"(p));
    return a;
}
__device__ __forceinline__ void cp_async16(uint32_t saddr, const void* g) {
    asm volatile("cp.async.cg.shared.global [%0], [%1], 16;" :: "r"(saddr), "l"(g));
}
#define CP_COMMIT() asm volatile("cp.async.commit_group;" ::: "memory")
#define CP_WAIT0()  asm volatile("cp.async.wait_group 0;" ::: "memory")
#define CP_WAIT1()  asm volatile("cp.async.wait_group 1;" ::: "memory")

__device__ __forceinline__ void mma_bf16(float* c, const uint32_t* a, const uint32_t* b) {
    asm volatile("mma.sync.aligned.m16n8k16.row.col.f32.bf16.bf16.f32 "
        "{%0,%1,%2,%3}, {%4,%5,%6,%7}, {%8,%9}, {%0,%1,%2,%3};"
        : "+f"(c[0]), "+f"(c[1]), "+f"(c[2]), "+f"(c[3])
        : "r"(a[0]), "r"(a[1]), "r"(a[2]), "r"(a[3]), "r"(b[0]), "r"(b[1]));
}
__device__ __forceinline__ void ldsm_x4(uint32_t* r, uint32_t addr) {
    asm volatile("ldmatrix.sync.aligned.m8n8.x4.shared.b16 {%0,%1,%2,%3}, [%4];"
        : "=r"(r[0]), "=r"(r[1]), "=r"(r[2]), "=r"(r[3]) : "r"(addr));
}
__device__ __forceinline__ void split2(float f0, float f1, uint32_t& hi, uint32_t& lo) {
    __nv_bfloat16 h0 = __float2bfloat16(f0), h1 = __float2bfloat16(f1);
    __nv_bfloat162 hh(h0, h1);
    hi = *(uint32_t*)&hh;
    __nv_bfloat16 l0 = __float2bfloat16(f0 - __bfloat162float(h0));
    __nv_bfloat16 l1 = __float2bfloat16(f1 - __bfloat162float(h1));
    __nv_bfloat162 ll(l0, l1);
    lo = *(uint32_t*)&ll;
}
__device__ __forceinline__ bool rd_mask(const unsigned char* p, long idx, int mt) {
    if (mt == 0) return p[idx] != 0;
    if (mt == 1) return ((const int*)p)[idx] != 0;
    return ((const float*)p)[idx] != 0.0f;
}
__device__ __forceinline__ uint32_t swz(uint32_t base, int r, int c) {
    return base + (uint32_t)r*64u + (uint32_t)((c ^ ((r >> 1) & 3)) << 4);
}

// ---------------- fused pre-processing kernel ----------------
#define NXB 4608
#define NPB 576
#define NTB 3840
#define NAB 288

__global__ void pre_kernel(const float* __restrict__ x, const float* __restrict__ pos,
                           const float* __restrict__ Wq, const float* __restrict__ Wk,
                           const float* __restrict__ Wv, const float* __restrict__ Wo,
                           const float* __restrict__ Wrel,
                           const unsigned char* __restrict__ lm,
                           const unsigned char* __restrict__ isg)
{
    __shared__ float t[32][33];
    __shared__ unsigned int cg[8];
    __shared__ unsigned char anyA[8];
    const int id = blockIdx.x;
    const int tid = threadIdx.x;

    if (id == 0 && tid < 16) g_cnt[tid] = 0u;   // reset split counters each run

    if (id < NXB + NPB) {
        const float* s; __nv_bfloat16 *h, *l; int n4, base;
        if (id < NXB) { s = x; h = g_xh; l = g_xl; n4 = B_*N_*DIM_/4; base = id; }
        else          { s = pos; h = g_ph; l = g_pl2; n4 = P_*192/4; base = id - NXB; }
        int i = base*256 + tid;
        if (i >= n4) return;
        float4 v = ((const float4*)s)[i];
        float a[4] = {v.x, v.y, v.z, v.w};
        __nv_bfloat16 hh[4], ll[4];
        #pragma unroll
        for (int j = 0; j < 4; j++) {
            hh[j] = __float2bfloat16(a[j]);
            ll[j] = __float2bfloat16(a[j] - __bfloat162float(hh[j]));
        }
        ((__nv_bfloat162*)h)[i*2+0] = __nv_bfloat162(hh[0], hh[1]);
        ((__nv_bfloat162*)h)[i*2+1] = __nv_bfloat162(hh[2], hh[3]);
        ((__nv_bfloat162*)l)[i*2+0] = __nv_bfloat162(ll[0], ll[1]);
        ((__nv_bfloat162*)l)[i*2+1] = __nv_bfloat162(ll[2], ll[3]);
    } else if (id < NXB + NPB + NTB) {
        int idx2 = id - NXB - NPB;
        int job = idx2 / 768, idx = idx2 % 768;
        const float* src; __nv_bfloat16 *dh, *dl;
        int R, C, c0, r0;
        if (job < 3) {
            src = (job == 0) ? Wq : (job == 1) ? Wk : Wv;
            dh = g_wh + (long)job*512*1536; dl = g_wl + (long)job*512*1536;
            R = 1536; C = 512;
            c0 = (idx & 15)*32; r0 = (idx >> 4)*32;
        } else if (job == 3) {
            src = Wo; dh = g_woh; dl = g_wol;
            R = 512; C = 1536;
            c0 = (idx % 48)*32; r0 = (idx / 48)*32;
        } else {
            if (idx >= 96) return;
            src = Wrel; dh = g_wrh; dl = g_wrl;
            R = 192; C = 512;
            c0 = (idx & 15)*32; r0 = (idx >> 4)*32;
        }
        int tx = tid & 31, ty = tid >> 5;
        #pragma unroll
        for (int i = 0; i < 4; i++)
            t[ty + i*8][tx] = src[(long)(r0 + ty + i*8)*C + c0 + tx];
        __syncthreads();
        #pragma unroll
        for (int i = 0; i < 4; i++) {
            int c = c0 + ty + i*8, r = r0 + tx;
            float v = t[tx][ty + i*8];
            __nv_bfloat16 hv = __float2bfloat16(v);
            dh[(long)c*R + r] = hv;
            dl[(long)c*R + r] = __float2bfloat16(v - __bfloat162float(hv));
        }
    } else {
        int tb = id - NXB - NPB - NTB;
        int g  = tid >> 6;
        int r  = tid & 63;
        int w  = tid >> 5;
        int lane = tid & 31;
        int tt = tb*4 + g;
        int jt = tt % QT_;
        int qt = (tt / QT_) % QT_;
        int b  = tt / (QT_*QT_);
        int i0 = qt*64, j0 = jt*64;
        unsigned int w0 = *(const unsigned int*)lm;
        int mt;
        if ((w0 & 0xFFu) == 1u && ((w0 >> 8) & 0xFFu) == 1u) mt = 0;
        else if (w0 == 1u) mt = 1;
        else mt = 2;

        bool cpred = rd_mask(isg, (long)b*N_ + j0 + r, mt);
        unsigned int cw = __ballot_sync(0xffffffffu, cpred);
        if (lane == 0) cg[w] = cw;

        bool rg = rd_mask(isg, (long)b*N_ + i0 + r, mt);

        unsigned long long rowbits = 0ull;
        if (mt == 0) {
            const uint4* rp = (const uint4*)(lm + (long)(i0 + r)*N_ + j0);
            #pragma unroll
            for (int q = 0; q < 4; q++) {
                uint4 v = rp[q];
                unsigned int ws[4] = {v.x, v.y, v.z, v.w};
                #pragma unroll
                for (int k = 0; k < 4; k++) {
                    unsigned int nz  = __vcmpne4(ws[k], 0u) & 0x01010101u;
                    unsigned int nib = (nz * 0x01020408u) >> 24;
                    rowbits |= (unsigned long long)(nib & 0xFu) << (q*16 + k*4);
                }
            }
        } else {
            for (int c = 0; c < 64; c++)
                rowbits |= (unsigned long long)(rd_mask(lm, (long)(i0+r)*N_ + j0 + c, mt) ? 1 : 0) << c;
        }
        __syncthreads();
        unsigned long long colbits = (unsigned long long)cg[g*2]
                                   | ((unsigned long long)cg[g*2+1] << 32);
        unsigned long long bits = rg ? ~0ull : (rowbits | colbits);
        g_mbits[(long)tt*64 + r] = bits;
        unsigned int anyw = __ballot_sync(0xffffffffu, bits != 0ull);
        if (lane == 0) anyA[w] = anyw ? 1 : 0;
        __syncthreads();
        if (r == 0) g_tact[tt] = (unsigned char)(anyA[g*2] | anyA[g*2+1]);
    }
}

// ---------------- warp-MMA bf16 split-precision GEMM (3-stage, swizzled) ----------------
#define TBYTES 8192
#define STAGE  (4*TBYTES)
#define NSTG   3
#define WG_SMEM (NSTG*STAGE)

__global__ __launch_bounds__(256, 2)
void wmma_gemm(const __nv_bfloat16* __restrict__ Ah, const __nv_bfloat16* __restrict__ Al,
               const __nv_bfloat16* __restrict__ Bh, const __nv_bfloat16* __restrict__ Bl,
               const float* __restrict__ bias, const float* __restrict__ bias2,
               float* __restrict__ Cout, int K, int mode)
{
    extern __shared__ char smem[];
    const uint32_t sb = smem_to_u32(smem);
    const int tid = threadIdx.x;
    const int lane = tid & 31;
    const int wid = tid >> 5;
    const int warp_m = wid >> 2;
    const int warp_n = wid & 3;
    const int grp = lane >> 2;
    const int tig = lane & 3;

    int m0, n0, Keff = K, mode_eff = mode;
    const char* srcs[4];
    if (mode == 0) {
        int id = blockIdx.x;
        if (id < 288) {
            m0 = (id % 24) * 128; n0 = (id / 24) * 128;
            srcs[0] = (const char*)Ah; srcs[1] = (const char*)Al;
            srcs[2] = (const char*)Bh; srcs[3] = (const char*)Bl;
        } else {
            id -= 288;
            m0 = (id % 24) * 128; n0 = (id / 24) * 128;
            srcs[0] = (const char*)g_ph;  srcs[1] = (const char*)g_pl2;
            srcs[2] = (const char*)g_wrh; srcs[3] = (const char*)g_wrl;
            Keff = 192; mode_eff = 2;
        }
    } else {
        m0 = blockIdx.x * 128; n0 = blockIdx.y * 128;
        srcs[0] = (const char*)Ah; srcs[1] = (const char*)Al;
        srcs[2] = (const char*)Bh; srcs[3] = (const char*)Bl;
    }

    const int arow_l = lane & 15;
    const int achk_l = lane >> 4;
    const int brow_l = ((lane >> 4) << 3) + (lane & 7);
    const int bchk_l = (lane >> 3) & 1;

    const int rb[4] = {m0, m0, n0, n0};
    const long rowB = (long)Keff * 2;

    auto issue_stage = [&](int kt, int st) {
        const uint32_t sbase = sb + st*STAGE;
        #pragma unroll
        for (int l = 0; l < 8; l++) {
            int i = tid + l*256;
            int t = i >> 9, r = (i >> 2) & 127, c = i & 3;
            const char* g = srcs[t] + (long)(rb[t] + r)*rowB + kt*64 + c*16;
            cp_async16(swz(sbase + t*TBYTES, r, c), g);
        }
        CP_COMMIT();
    };

    float acc[4][4][4];
    #pragma unroll
    for (int i = 0; i < 4; i++)
        #pragma unroll
        for (int j = 0; j < 4; j++)
            #pragma unroll
            for (int e = 0; e < 4; e++) acc[i][j][e] = 0.f;

    const int nk = Keff / 32;
    issue_stage(0, 0);
    issue_stage(1, 1);

    for (int kt = 0; kt < nk; kt++) {
        CP_WAIT1();
        __syncthreads();
        if (kt + 2 < nk) issue_stage(kt + 2, (kt + 2) % NSTG);

        const uint32_t stg = sb + (kt % NSTG)*STAGE;
        const uint32_t aoffh = stg + 0*TBYTES;
        const uint32_t aoffl = stg + 1*TBYTES;
        const uint32_t boffh = stg + 2*TBYTES;
        const uint32_t boffl = stg + 3*TBYTES;

        #pragma unroll
        for (int ks = 0; ks < 2; ks++) {
            uint32_t bh[4][2], bl[4][2];
            #pragma unroll
            for (int jp = 0; jp < 2; jp++) {
                int brw = warp_n*32 + jp*16 + brow_l;
                int bck = ks*2 + bchk_l;
                uint32_t r4[4];
                ldsm_x4(r4, swz(boffh, brw, bck));
                bh[2*jp][0] = r4[0]; bh[2*jp][1] = r4[1];
                bh[2*jp+1][0] = r4[2]; bh[2*jp+1][1] = r4[3];
                ldsm_x4(r4, swz(boffl, brw, bck));
                bl[2*jp][0] = r4[0]; bl[2*jp][1] = r4[1];
                bl[2*jp+1][0] = r4[2]; bl[2*jp+1][1] = r4[3];
            }
            #pragma unroll
            for (int i = 0; i < 4; i++) {
                int arw = warp_m*64 + i*16 + arow_l;
                int ack = ks*2 + achk_l;
                uint32_t ah[4], al[4];
                ldsm_x4(ah, swz(aoffh, arw, ack));
                ldsm_x4(al, swz(aoffl, arw, ack));
                #pragma unroll
                for (int j = 0; j < 4; j++) mma_bf16(acc[i][j], ah, bh[j]);
                #pragma unroll
                for (int j = 0; j < 4; j++) mma_bf16(acc[i][j], ah, bl[j]);
                #pragma unroll
                for (int j = 0; j < 4; j++) mma_bf16(acc[i][j], al, bh[j]);
            }
        }
    }

    // epilogue
    #pragma unroll
    for (int i = 0; i < 4; i++) {
        #pragma unroll
        for (int j = 0; j < 4; j++) {
            const int r0 = m0 + warp_m*64 + i*16 + grp;
            const int c0 = n0 + warp_n*32 + j*8 + 2*tig;
            #pragma unroll
            for (int half = 0; half < 2; half++) {
                const int row = r0 + half*8;
                float v0 = acc[i][j][half*2 + 0];
                float v1 = acc[i][j][half*2 + 1];
                if (mode_eff == 1) {
                    Cout[(long)row*1536 + c0]     = v0 + bias[c0];
                    Cout[(long)row*1536 + c0 + 1] = v1 + bias[c0 + 1];
                } else if (mode_eff == 2) {
                    const int h = c0 >> 6, d = c0 & 63;
                    uint32_t hi, lo; split2(v0, v1, hi, lo);
                    long idx = ((long)h*RP_ + row)*D_ + d;
                    *(uint32_t*)&g_rh[idx] = hi;
                    *(uint32_t*)&g_rl[idx] = lo;
                } else {
                    const int sel = c0 >> 9, pc = c0 & 511;
                    const int h = pc >> 6, d = pc & 63;
                    const int bb = (row >= N_) ? 1 : 0;
                    const int ii = row - bb*N_;
                    const int bhd = bb*H_ + h;
                    if (sel == 0) {
                        float s0 = v0*0.125f, s1 = v1*0.125f;
                        long idx = ((long)bhd*N_ + ii)*D_ + d;
                        uint32_t hi, lo;
                        split2(s0 + bias[pc], s1 + bias[pc + 1], hi, lo);
                        *(uint32_t*)&g_qh[idx] = hi;
                        *(uint32_t*)&g_ql[idx] = lo;
                        split2(s0 + bias2[pc], s1 + bias2[pc + 1], hi, lo);
                        *(uint32_t*)&g_qph[idx] = hi;
                        *(uint32_t*)&g_qpl[idx] = lo;
                    } else if (sel == 1) {
                        uint32_t hi, lo; split2(v0, v1, hi, lo);
                        long idx = ((long)bhd*N_ + ii)*D_ + d;
                        *(uint32_t*)&g_kh[idx] = hi;
                        *(uint32_t*)&g_kl[idx] = lo;
                    } else {
                        __nv_bfloat16 h0 = __float2bfloat16(v0);
                        __nv_bfloat16 h1 = __float2bfloat16(v1);
                        long i0x = ((long)bhd*D_ + d)*N_ + ii;
                        long i1x = ((long)bhd*D_ + d + 1)*N_ + ii;
                        g_vth[i0x] = h0;
                        g_vth[i1x] = h1;
                        g_vtl[i0x] = __float2bfloat16(v0 - __bfloat162float(h0));
                        g_vtl[i1x] = __float2bfloat16(v1 - __bfloat162float(h1));
                    }
                }
            }
        }
    }
}

// ---------------- mma.sync flash attention (banded G + split-KV + fused merge) ----------------
#define AK_H   0u
#define AK_L   9216u
#define AVT_H  18432u
#define AVT_L  27648u
#define AR_H   36864u
#define AR_L   55296u
#define AG     73728u
#define ATTN2_SMEM (73728 + 64*132*4)

__global__ __launch_bounds__(128, 2)
void attn_mma()
{
    extern __shared__ char sm2[];
    const uint32_t sb = smem_to_u32(sm2);
    float* sG = (float*)(sm2 + AG);
    __shared__ unsigned int sLast;

    const int tid = threadIdx.x;
    const int lane = tid & 31;
    const int w = tid >> 5;
    const int grp = lane >> 2;
    const int tig = lane & 3;
    const int qs = blockIdx.x;          // 0..24+NSP-2
    const int bh = blockIdx.y;
    const int b = bh >> 3, h = bh & 7;

    int qt, sp, jt_lo, jt_hi;
    if (qs < 24) { qt = qs; sp = 0; } else { qt = 0; sp = qs - 23; }
    if (qt == 0) { jt_lo = sp*(QT_/NSP); jt_hi = jt_lo + (QT_/NSP); }
    else         { jt_lo = 0; jt_hi = QT_; }
    const int i0 = qt * 64;

    const int brow_l = ((lane >> 4) << 3) + (lane & 7);
    const int bcol_l = ((lane >> 3) & 1) * 16;
    const int gb_lo = 3 - w;
    const int gb_hi = 7 - w;

    const __nv_bfloat16* qbh = g_qh  + (long)bh*N_*D_;
    const __nv_bfloat16* qbl = g_ql  + (long)bh*N_*D_;
    const __nv_bfloat16* pqh = g_qph + (long)bh*N_*D_;
    const __nv_bfloat16* pql = g_qpl + (long)bh*N_*D_;
    const int rq0 = i0 + w*16 + grp, rq1 = rq0 + 8;
    uint32_t qfh[4][4], qfl[4][4], qgh[4][4], qgl[4][4];
    #pragma unroll
    for (int kf = 0; kf < 4; kf++) {
        qfh[kf][0] = *(const uint32_t*)(qbh + (long)rq0*D_ + kf*16 + 2*tig);
        qfh[kf][1] = *(const uint32_t*)(qbh + (long)rq1*D_ + kf*16 + 2*tig);
        qfh[kf][2] = *(const uint32_t*)(qbh + (long)rq0*D_ + kf*16 + 8 + 2*tig);
        qfh[kf][3] = *(const uint32_t*)(qbh + (long)rq1*D_ + kf*16 + 8 + 2*tig);
        qfl[kf][0] = *(const uint32_t*)(qbl + (long)rq0*D_ + kf*16 + 2*tig);
        qfl[kf][1] = *(const uint32_t*)(qbl + (long)rq1*D_ + kf*16 + 2*tig);
        qfl[kf][2] = *(const uint32_t*)(qbl + (long)rq0*D_ + kf*16 + 8 + 2*tig);
        qfl[kf][3] = *(const uint32_t*)(qbl + (long)rq1*D_ + kf*16 + 8 + 2*tig);
        qgh[kf][0] = *(const uint32_t*)(pqh + (long)rq0*D_ + kf*16 + 2*tig);
        qgh[kf][1] = *(const uint32_t*)(pqh + (long)rq1*D_ + kf*16 + 2*tig);
        qgh[kf][2] = *(const uint32_t*)(pqh + (long)rq0*D_ + kf*16 + 8 + 2*tig);
        qgh[kf][3] = *(const uint32_t*)(pqh + (long)rq1*D_ + kf*16 + 8 + 2*tig);
        qgl[kf][0] = *(const uint32_t*)(pql + (long)rq0*D_ + kf*16 + 2*tig);
        qgl[kf][1] = *(const uint32_t*)(pql + (long)rq1*D_ + kf*16 + 2*tig);
        qgl[kf][2] = *(const uint32_t*)(pql + (long)rq0*D_ + kf*16 + 8 + 2*tig);
        qgl[kf][3] = *(const uint32_t*)(pql + (long)rq1*D_ + kf*16 + 8 + 2*tig);
    }

    float o[8][4];
    #pragma unroll
    for (int nf = 0; nf < 8; nf++)
        #pragma unroll
        for (int e = 0; e < 4; e++) o[nf][e] = 0.f;
    float mrow[2] = {-1e30f, -1e30f};
    float lrow[2] = {0.f, 0.f};

    const unsigned char* tact = &g_tact[(b*QT_ + qt)*QT_];
    const long kbase  = (long)bh*N_*D_;
    const long vbase  = (long)bh*D_*N_;
    const long rbase  = (long)h*RP_*D_;

    for (int jt = jt_lo; jt < jt_hi; jt++) {
        if (!tact[jt]) continue;
        const int j0 = jt*64;
        const int p0 = j0 - i0 + (N_ - 1) - 63;

        __syncthreads();
        #pragma unroll
        for (int l = 0; l < 4; l++) {
            int i = tid + l*128;
            int r = i >> 3, c = i & 7;
            long krow = (kbase + (long)(j0 + r)*D_)*2;
            long vrow = (vbase + (long)r*N_ + j0)*2;
            cp_async16(sb + AK_H  + r*144 + c*16, (const char*)g_kh  + krow + c*16);
            cp_async16(sb + AK_L  + r*144 + c*16, (const char*)g_kl  + krow + c*16);
            cp_async16(sb + AVT_H + r*144 + c*16, (const char*)g_vth + vrow + c*16);
            cp_async16(sb + AVT_L + r*144 + c*16, (const char*)g_vtl + vrow + c*16);
        }
        #pragma unroll
        for (int l = 0; l < 8; l++) {
            int i = tid + l*128;
            int r = i >> 3, c = i & 7;
            long rrow = (rbase + (long)(p0 + r)*D_)*2;
            cp_async16(sb + AR_H + r*144 + c*16, (const char*)g_rh + rrow + c*16);
            cp_async16(sb + AR_L + r*144 + c*16, (const char*)g_rl + rrow + c*16);
        }
        CP_COMMIT();

        const unsigned long long* mb = g_mbits + ((long)(b*QT_ + qt)*QT_ + jt)*64;
        unsigned long long mw0 = mb[w*16 + grp];
        unsigned long long mw1 = mb[w*16 + grp + 8];

        CP_WAIT0();
        __syncthreads();

        float ca[8][4];
        #pragma unroll
        for (int nf = 0; nf < 8; nf++)
            #pragma unroll
            for (int e = 0; e < 4; e++) ca[nf][e] = 0.f;
        #pragma unroll
        for (int kf = 0; kf < 4; kf++) {
            #pragma unroll
            for (int np = 0; np < 4; np++) {
                uint32_t ro = (uint32_t)(np*16 + brow_l)*144 + kf*32 + bcol_l;
                uint32_t kh4[4], kl4[4];
                ldsm_x4(kh4, sb + AK_H + ro);
                ldsm_x4(kl4, sb + AK_L + ro);
                mma_bf16(ca[2*np],   qfh[kf], &kh4[0]);
                mma_bf16(ca[2*np+1], qfh[kf], &kh4[2]);
                mma_bf16(ca[2*np],   qfh[kf], &kl4[0]);
                mma_bf16(ca[2*np+1], qfh[kf], &kl4[2]);
                mma_bf16(ca[2*np],   qfl[kf], &kh4[0]);
                mma_bf16(ca[2*np+1], qfl[kf], &kh4[2]);
            }
        }

        const int grow = w*16 + grp;
        #pragma unroll
        for (int gh = 0; gh < 2; gh++) {
            #pragma unroll
            for (int np = 0; np < 4; np++) {
                const int gb = gh*4 + np;
                if (gb < gb_lo || gb > gb_hi) continue;
                float ga0[4] = {0.f, 0.f, 0.f, 0.f};
                float ga1[4] = {0.f, 0.f, 0.f, 0.f};
                #pragma unroll
                for (int kf = 0; kf < 4; kf++) {
                    uint32_t ro = (uint32_t)(gb*16 + brow_l)*144 + kf*32 + bcol_l;
                    uint32_t rh4[4], rl4[4];
                    ldsm_x4(rh4, sb + AR_H + ro);
                    ldsm_x4(rl4, sb + AR_L + ro);
                    mma_bf16(ga0, qgh[kf], &rh4[0]);
                    mma_bf16(ga1, qgh[kf], &rh4[2]);
                    mma_bf16(ga0, qgh[kf], &rl4[0]);
                    mma_bf16(ga1, qgh[kf], &rl4[2]);
                    mma_bf16(ga0, qgl[kf], &rh4[0]);
                    mma_bf16(ga1, qgl[kf], &rh4[2]);
                }
                int col = gb*16 + 2*tig;
                sG[grow*132 + col]            = ga0[0];
                sG[grow*132 + col + 1]        = ga0[1];
                sG[(grow + 8)*132 + col]      = ga0[2];
                sG[(grow + 8)*132 + col + 1]  = ga0[3];
                sG[grow*132 + col + 8]        = ga1[0];
                sG[grow*132 + col + 9]        = ga1[1];
                sG[(grow + 8)*132 + col + 8]  = ga1[2];
                sG[(grow + 8)*132 + col + 9]  = ga1[3];
            }
        }
        __syncwarp();

        float pv0[16], pv1[16];
        #pragma unroll
        for (int h2 = 0; h2 < 2; h2++) {
            const int rl = grow + 8*h2;
            const unsigned long long mw = h2 ? mw1 : mw0;
            float* pvv = h2 ? pv1 : pv0;
            float lg[16];
            float tmax = -1e30f;
            #pragma unroll
            for (int nf = 0; nf < 8; nf++) {
                #pragma unroll
                for (int e = 0; e < 2; e++) {
                    int c = 8*nf + 2*tig + e;
                    int pp = c - rl + 63;
                    float val = ca[nf][2*h2 + e] + sG[rl*132 + pp];
                    bool act = (mw >> c) & 1ull;
                    float lv = act ? val : -1e30f;
                    lg[nf*2 + e] = lv;
                    tmax = fmaxf(tmax, lv);
                }
            }
            tmax = fmaxf(tmax, __shfl_xor_sync(0xffffffffu, tmax, 1));
            tmax = fmaxf(tmax, __shfl_xor_sync(0xffffffffu, tmax, 2));
            float nm = fmaxf(mrow[h2], tmax);
            float corr = __expf(mrow[h2] - nm);
            mrow[h2] = nm;
            float ps = 0.f;
            #pragma unroll
            for (int e2 = 0; e2 < 16; e2++) {
                float p = (lg[e2] <= -1e29f) ? 0.f : __expf(lg[e2] - nm);
                pvv[e2] = p;
                ps += p;
            }
            ps += __shfl_xor_sync(0xffffffffu, ps, 1);
            ps += __shfl_xor_sync(0xffffffffu, ps, 2);
            lrow[h2] = lrow[h2]*corr + ps;
            #pragma unroll
            for (int nf = 0; nf < 8; nf++) {
                o[nf][2*h2]     *= corr;
                o[nf][2*h2 + 1] *= corr;
            }
        }

        uint32_t pfh[4][4], pfl[4][4];
        #pragma unroll
        for (int kf = 0; kf < 4; kf++) {
            split2(pv0[(2*kf)*2],   pv0[(2*kf)*2+1],   pfh[kf][0], pfl[kf][0]);
            split2(pv1[(2*kf)*2],   pv1[(2*kf)*2+1],   pfh[kf][1], pfl[kf][1]);
            split2(pv0[(2*kf+1)*2], pv0[(2*kf+1)*2+1], pfh[kf][2], pfl[kf][2]);
            split2(pv1[(2*kf+1)*2], pv1[(2*kf+1)*2+1], pfh[kf][3], pfl[kf][3]);
        }

        #pragma unroll
        for (int kf = 0; kf < 4; kf++) {
            #pragma unroll
            for (int np = 0; np < 4; np++) {
                uint32_t ro = (uint32_t)(np*16 + brow_l)*144 + kf*32 + bcol_l;
                uint32_t vh4[4], vl4[4];
                ldsm_x4(vh4, sb + AVT_H + ro);
                ldsm_x4(vl4, sb + AVT_L + ro);
                mma_bf16(o[2*np],   pfh[kf], &vh4[0]);
                mma_bf16(o[2*np+1], pfh[kf], &vh4[2]);
                mma_bf16(o[2*np],   pfh[kf], &vl4[0]);
                mma_bf16(o[2*np+1], pfh[kf], &vl4[2]);
                mma_bf16(o[2*np],   pfl[kf], &vh4[0]);
                mma_bf16(o[2*np+1], pfl[kf], &vh4[2]);
            }
        }
    }

    // ---- epilogue ----
    if (qt == 0) {
        // store unnormalized partials, then last-arriving split merges in-kernel
        const long pbase = ((long)bh*NSP + sp)*64*64;
        #pragma unroll
        for (int h2 = 0; h2 < 2; h2++) {
            int rl = w*16 + grp + 8*h2;
            if (tig == 0) {
                g_pm[((long)bh*NSP + sp)*64 + rl] = mrow[h2];
                g_pl[((long)bh*NSP + sp)*64 + rl] = lrow[h2];
            }
            #pragma unroll
            for (int nf = 0; nf < 8; nf++) {
                g_po[pbase + (long)rl*64 + 8*nf + 2*tig]     = o[nf][2*h2];
                g_po[pbase + (long)rl*64 + 8*nf + 2*tig + 1] = o[nf][2*h2 + 1];
            }
        }
        __threadfence();
        __syncthreads();
        if (tid == 0)
            sLast = (atomicAdd(&g_cnt[bh], 1u) == (unsigned)(NSP - 1)) ? 1u : 0u;
        __syncthreads();
        if (sLast) {
            float* sCf = (float*)sm2;            // reuse tile smem (all warps past loop)
            float* sLx = sCf + NSP*64;
            if (tid < 64) {
                float m = -1e30f;
                #pragma unroll
                for (int s = 0; s < NSP; s++)
                    m = fmaxf(m, g_pm[((long)bh*NSP + s)*64 + tid]);
                float l = 0.f;
                #pragma unroll
                for (int s = 0; s < NSP; s++) {
                    float ms = g_pm[((long)bh*NSP + s)*64 + tid];
                    float cf = (ms > -1e29f) ? __expf(ms - m) : 0.f;
                    sCf[s*64 + tid] = cf;
                    l += cf * g_pl[((long)bh*NSP + s)*64 + tid];
                }
                sLx[tid] = l;
            }
            __syncthreads();
            for (int it = tid; it < 64*32; it += 128) {
                int r = it >> 5, cp = (it & 31)*2;
                float a0 = 0.f, a1 = 0.f;
                #pragma unroll
                for (int s = 0; s < NSP; s++) {
                    float cf = sCf[s*64 + r];
                    if (cf != 0.f) {
                        const float* po = &g_po[(((long)bh*NSP + s)*64 + r)*64 + cp];
                        a0 += cf*po[0];
                        a1 += cf*po[1];
                    }
                }
                float inv = 1.0f / sLx[r];
                uint32_t hi, lo; split2(a0*inv, a1*inv, hi, lo);
                long idx = ((long)(b*N_ + r))*(H_*D_) + h*D_ + cp;
                *(uint32_t*)&g_ah[idx] = hi;
                *(uint32_t*)&g_al[idx] = lo;
            }
        }
    } else {
        #pragma unroll
        for (int h2 = 0; h2 < 2; h2++) {
            float inv = 1.0f / lrow[h2];
            int rl = w*16 + grp + 8*h2;
            long rowbase = ((long)(b*N_ + i0 + rl))*(H_*D_) + h*D_;
            #pragma unroll
            for (int nf = 0; nf < 8; nf++) {
                float f0 = o[nf][2*h2]     * inv;
                float f1 = o[nf][2*h2 + 1] * inv;
                uint32_t hi, lo; split2(f0, f1, hi, lo);
                long idx = rowbase + 8*nf + 2*tig;
                *(uint32_t*)&g_ah[idx] = hi;
                *(uint32_t*)&g_al[idx] = lo;
            }
        }
    }
}

// ---------------- launcher ----------------
extern "C" void kernel_launch(void* const* d_in, const int* in_sizes, int n_in,
                              void* d_out, int out_size)
{
    const float* x    = (const float*)d_in[0];
    const float* Wq   = (const float*)d_in[1];
    const float* Wk   = (const float*)d_in[2];
    const float* Wv   = (const float*)d_in[3];
    const float* Wrel = (const float*)d_in[4];
    const float* cb   = (const float*)d_in[5];
    const float* pb   = (const float*)d_in[6];
    const float* Wo   = (const float*)d_in[7];
    const float* bo   = (const float*)d_in[8];
    const float* pos  = (const float*)d_in[9];
    const unsigned char* lmu = (const unsigned char*)d_in[10];
    const unsigned char* isg = (const unsigned char*)d_in[11];
    float* out = (float*)d_out;

    cudaFuncSetAttribute(wmma_gemm, cudaFuncAttributeMaxDynamicSharedMemorySize, WG_SMEM);
    cudaFuncSetAttribute(attn_mma, cudaFuncAttributeMaxDynamicSharedMemorySize, ATTN2_SMEM);

    __nv_bfloat16 *xh_p, *xl_p, *wh_p, *wl_p, *woh_p, *wol_p, *ah_p, *al_p;
    cudaGetSymbolAddress((void**)&xh_p,  g_xh);
    cudaGetSymbolAddress((void**)&xl_p,  g_xl);
    cudaGetSymbolAddress((void**)&wh_p,  g_wh);
    cudaGetSymbolAddress((void**)&wl_p,  g_wl);
    cudaGetSymbolAddress((void**)&woh_p, g_woh);
    cudaGetSymbolAddress((void**)&wol_p, g_wol);
    cudaGetSymbolAddress((void**)&ah_p,  g_ah);
    cudaGetSymbolAddress((void**)&al_p,  g_al);

    pre_kernel<<<NXB + NPB + NTB + NAB, 256>>>(x, pos, Wq, Wk, Wv, Wo, Wrel,
                                               lmu, isg);                    // 1
    wmma_gemm<<<384, 256, WG_SMEM>>>(xh_p, xl_p, wh_p, wl_p,
                                     cb, pb, nullptr, DIM_, 0);              // 2
    attn_mma<<<dim3(24 + NSP - 1, B_*H_), 128, ATTN2_SMEM>>>();              // 3
    wmma_gemm<<<dim3(24, 12), 256, WG_SMEM>>>(ah_p, al_p, woh_p, wol_p,
                                              bo, nullptr, out, 512, 1);     // 4
}